// round 11
// baseline (speedup 1.0000x reference)
#include <cuda_runtime.h>
#include <cuda_bf16.h>
#include <cstdint>

#define HHn 8
#define LLn 128
#define DDn 512
#define DIn 2048
#define NBS 128
#define NROW 1024

typedef unsigned long long u64;

// ---------------- scratch (device globals; no allocation allowed) ----------
__device__ float g_o  [NROW*DDn];
__device__ float g_logits[NROW*LLn];
__device__ float g_p  [4][NROW*DDn];    // split-K partials
__device__ __nv_bfloat16 g_axh[NROW*DDn];
__device__ __nv_bfloat16 g_axl[NROW*DDn];
__device__ __nv_bfloat16 g_oh [NROW*DDn];
__device__ __nv_bfloat16 g_ol [NROW*DDn];
__device__ __nv_bfloat16 g_hh [NROW*DIn];
__device__ __nv_bfloat16 g_hl [NROW*DIn];
__device__ __nv_bfloat16 g_vwh[DDn*DDn];
__device__ __nv_bfloat16 g_vwl[DDn*DDn];
__device__ __nv_bfloat16 g_w1h[DIn*DDn];
__device__ __nv_bfloat16 g_w1l[DIn*DDn];
__device__ __nv_bfloat16 g_w2h[DDn*DIn];
__device__ __nv_bfloat16 g_w2l[DDn*DIn];

// ---------------- helpers ---------------------------------------------------
__device__ __forceinline__ uint32_t smem_u32(const void* p) {
    uint32_t a;
    asm("{ .reg .u64 t; cvta.to.shared.u64 t, %1; cvt.u32.u64 %0, t; }"
        : "=r"(a) : "l"(p));
    return a;
}
__device__ __forceinline__ void bsplit(float v, __nv_bfloat16& h, __nv_bfloat16& l) {
    h = __float2bfloat16(v);
    l = __float2bfloat16(v - __bfloat162float(h));
}
__device__ __forceinline__ void fma2(u64 &d, u64 a, u64 b) {
    asm("fma.rn.f32x2 %0, %1, %2, %0;" : "+l"(d) : "l"(a), "l"(b));
}
__device__ __forceinline__ u64 pk2(float a, float b) {
    u64 r; asm("mov.b64 %0, {%1,%2};" : "=l"(r) : "f"(a), "f"(b)); return r;
}
__device__ __forceinline__ float2 upk2(u64 v) {
    float2 r; asm("mov.b64 {%0,%1}, %2;" : "=f"(r.x), "=f"(r.y) : "l"(v)); return r;
}

#define CPA16(dst, src) \
    asm volatile("cp.async.cg.shared.global [%0], [%1], 16;" \
                 :: "r"(dst), "l"(src) : "memory")
#define CPA_COMMIT() asm volatile("cp.async.commit_group;" ::: "memory")
#define CPA_WAIT(n)  asm volatile("cp.async.wait_group %0;" :: "n"(n) : "memory")

#define LDSM4(r, addr) \
    asm volatile("ldmatrix.sync.aligned.m8n8.x4.shared.b16 {%0,%1,%2,%3}, [%4];" \
                 : "=r"((r)[0]), "=r"((r)[1]), "=r"((r)[2]), "=r"((r)[3]) \
                 : "r"(addr))

#define MMA_BF16(c, a, b) \
    asm volatile("mma.sync.aligned.m16n8k16.row.col.f32.bf16.bf16.f32 " \
        "{%0,%1,%2,%3}, {%4,%5,%6,%7}, {%8,%9}, {%0,%1,%2,%3};" \
        : "+f"((c)[0]), "+f"((c)[1]), "+f"((c)[2]), "+f"((c)[3]) \
        : "r"((a)[0]), "r"((a)[1]), "r"((a)[2]), "r"((a)[3]), \
          "r"((b)[0]), "r"((b)[1]))

// 128-byte smem rows (BK=64 bf16), 8 chunks of 16B, full 3-bit XOR swizzle.
__device__ __forceinline__ uint32_t tile_off(int row, int chunk) {
    return (uint32_t)(row * 128 + ((chunk ^ (row & 7)) << 4));
}

// ---------------------------------------------------------------------------
// HMMA split-bf16 GEMM. BK=64, 2-stage double buffer, 256 threads (8 warps).
// Dual accumulators (c1: hi*hi, c2: cross terms) to double MMA chain ILP.
// EPI=0: fp32 partial store to C + z*M*N (split-K over blockIdx.z).
// EPI=1: bias + relu + bf16 hi/lo split store.
// ---------------------------------------------------------------------------
template<int BM, int BN, int EPI>
__global__ __launch_bounds__(256, 2) void gemm_mma(
    const __nv_bfloat16* __restrict__ Ah, const __nv_bfloat16* __restrict__ Al,
    const __nv_bfloat16* __restrict__ Bh, const __nv_bfloat16* __restrict__ Bl,
    const float* __restrict__ bias, float* __restrict__ C,
    __nv_bfloat16* __restrict__ Ch, __nv_bfloat16* __restrict__ Cl,
    int M, int N, int K)
{
    constexpr int BK = 64, THREADS = 256;
    constexpr int WM = 2, WN = 4;
    constexpr int A_BYTES = BM * 128;
    constexpr int B_BYTES = BN * 128;
    constexpr int STAGE = 2 * A_BYTES + 2 * B_BYTES;
    constexpr int MT = (BM / WM) / 16;
    constexpr int NT = (BN / WN) / 8;
    constexpr int CHUNKS = (2 * BM + 2 * BN) * 8;
    constexpr int CPT = CHUNKS / THREADS;

    extern __shared__ __align__(128) char dsm[];
    const uint32_t sb = smem_u32(dsm);

    const int tid = threadIdx.x, wid = tid >> 5, lane = tid & 31;
    const int bm = blockIdx.y * BM, bn = blockIdx.x * BN;
    const int wm = wid / WN, wn = wid % WN;
    const int KT = (K / BK) / gridDim.z;
    const int kt0 = blockIdx.z * KT;

    auto load_stage = [&](int kt, int s) {
        const uint32_t base = sb + s * STAGE;
        const size_t gk = (size_t)(kt0 + kt) * BK;
        #pragma unroll
        for (int i = 0; i < CPT; i++) {
            int id = tid + i * THREADS;
            int row_all = id >> 3;
            int ck = id & 7;
            const __nv_bfloat16* g;
            uint32_t abase; int row; int rowbase;
            if (row_all < BM)            { g = Ah; abase = 0;                     row = row_all;            rowbase = bm; }
            else if (row_all < 2 * BM)   { g = Al; abase = A_BYTES;               row = row_all - BM;       rowbase = bm; }
            else if (row_all < 2*BM+BN)  { g = Bh; abase = 2 * A_BYTES;           row = row_all - 2 * BM;   rowbase = bn; }
            else                         { g = Bl; abase = 2 * A_BYTES + B_BYTES; row = row_all - 2*BM - BN; rowbase = bn; }
            const __nv_bfloat16* src =
                g + (size_t)(rowbase + row) * K + gk + ck * 8;
            CPA16(base + abase + tile_off(row, ck), src);
        }
        CPA_COMMIT();
    };

    float c1[MT][NT][4], c2[MT][NT][4];
    #pragma unroll
    for (int i = 0; i < MT; i++)
        #pragma unroll
        for (int j = 0; j < NT; j++)
            #pragma unroll
            for (int q = 0; q < 4; q++) { c1[i][j][q] = 0.f; c2[i][j][q] = 0.f; }

    load_stage(0, 0);
    CPA_WAIT(0);
    __syncthreads();

    const int aRow0 = wm * (BM / WM);
    const int bRow0 = wn * (BN / WN);

    for (int kt = 0; kt < KT; kt++) {
        if (kt + 1 < KT) load_stage(kt + 1, (kt + 1) & 1);

        const uint32_t base = sb + (kt & 1) * STAGE;
        const uint32_t sAh = base;
        const uint32_t sAl = base + A_BYTES;
        const uint32_t sBh = base + 2 * A_BYTES;
        const uint32_t sBl = base + 2 * A_BYTES + B_BYTES;

        #pragma unroll
        for (int ks = 0; ks < 4; ks++) {
            uint32_t aH[MT][4], aL[MT][4];
            #pragma unroll
            for (int mt = 0; mt < MT; mt++) {
                int row = aRow0 + mt * 16 + (lane & 15);
                int ck = ks * 2 + (lane >> 4);
                uint32_t off = tile_off(row, ck);
                LDSM4(aH[mt], sAh + off);
                LDSM4(aL[mt], sAl + off);
            }
            uint32_t bH[NT][2], bL[NT][2];
            #pragma unroll
            for (int p = 0; p < NT / 2; p++) {
                int row = bRow0 + p * 16 + (lane & 7) + ((lane >> 4) << 3);
                int ck = ks * 2 + ((lane >> 3) & 1);
                uint32_t off = tile_off(row, ck);
                uint32_t r[4];
                LDSM4(r, sBh + off);
                bH[2*p][0] = r[0]; bH[2*p][1] = r[1];
                bH[2*p+1][0] = r[2]; bH[2*p+1][1] = r[3];
                LDSM4(r, sBl + off);
                bL[2*p][0] = r[0]; bL[2*p][1] = r[1];
                bL[2*p+1][0] = r[2]; bL[2*p+1][1] = r[3];
            }
            // two independent accumulator sets -> 2x MMA chain ILP
            #pragma unroll
            for (int mt = 0; mt < MT; mt++)
                #pragma unroll
                for (int nt = 0; nt < NT; nt++) {
                    MMA_BF16(c1[mt][nt], aH[mt], bH[nt]);
                    MMA_BF16(c2[mt][nt], aH[mt], bL[nt]);
                    MMA_BF16(c2[mt][nt], aL[mt], bH[nt]);
                }
        }

        CPA_WAIT(0);
        __syncthreads();
    }

    // ---- epilogue ----
    float* Cz = C + (size_t)blockIdx.z * M * N;
    #pragma unroll
    for (int mt = 0; mt < MT; mt++) {
        #pragma unroll
        for (int nt = 0; nt < NT; nt++) {
            int row = bm + aRow0 + mt * 16 + (lane >> 2);
            int col = bn + bRow0 + nt * 8 + ((lane & 3) << 1);
            #pragma unroll
            for (int half = 0; half < 2; half++) {
                int r = row + half * 8;
                float v0 = c1[mt][nt][half * 2 + 0] + c2[mt][nt][half * 2 + 0];
                float v1 = c1[mt][nt][half * 2 + 1] + c2[mt][nt][half * 2 + 1];
                if (EPI == 0) {
                    Cz[(size_t)r * N + col]     = v0;
                    Cz[(size_t)r * N + col + 1] = v1;
                } else {
                    v0 = fmaxf(v0 + bias[col], 0.f);
                    v1 = fmaxf(v1 + bias[col + 1], 0.f);
                    __nv_bfloat16 h, l;
                    bsplit(v0, h, l);
                    Ch[(size_t)r * N + col] = h; Cl[(size_t)r * N + col] = l;
                    bsplit(v1, h, l);
                    Ch[(size_t)r * N + col + 1] = h; Cl[(size_t)r * N + col + 1] = l;
                }
            }
        }
    }
}

// ---------------------------------------------------------------------------
// K1: logits[bs][h][l] = sum_d x[bs,l,d] * w[h,l,d].  grid (l=128, half=2).
// ---------------------------------------------------------------------------
__global__ __launch_bounds__(256) void logits_kernel(
    const float* __restrict__ x, const float* __restrict__ w,
    float* __restrict__ logits)
{
    __shared__ __align__(16) float w_s[HHn][DDn];
    const int l = blockIdx.x, half = blockIdx.y;
    const int tid = threadIdx.x, warp = tid >> 5, lane = tid & 31;

    #pragma unroll
    for (int i = 0; i < 4; i++) {
        int idx = tid + i * 256;
        int h = idx >> 7, d4 = idx & 127;
        ((float4*)w_s[h])[d4] =
            ((const float4*)(w + ((size_t)(h * LLn + l)) * DDn))[d4];
    }
    __syncthreads();

    const int j  = __brev((unsigned)lane) >> 27;
    const int jb = j >> 3, jh = j & 7;

    #pragma unroll
    for (int q = 0; q < 2; q++) {
        const int bs0 = half * 64 + warp * 8 + q * 4;
        u64 acc[4][HHn];
        #pragma unroll
        for (int b = 0; b < 4; b++)
            #pragma unroll
            for (int h = 0; h < HHn; h++) acc[b][h] = 0ull;

        #pragma unroll
        for (int c = 0; c < 4; c++) {
            const int d4 = c * 32 + lane;
            u64 xp[4][2];
            #pragma unroll
            for (int b = 0; b < 4; b++) {
                double2 xv = ((const double2*)
                    (x + ((size_t)((bs0 + b) * LLn + l)) * DDn))[d4];
                xp[b][0] = __double_as_longlong(xv.x);
                xp[b][1] = __double_as_longlong(xv.y);
            }
            #pragma unroll
            for (int h = 0; h < HHn; h++) {
                double2 wv = ((const double2*)w_s[h])[d4];
                u64 w0 = __double_as_longlong(wv.x);
                u64 w1 = __double_as_longlong(wv.y);
                #pragma unroll
                for (int b = 0; b < 4; b++) {
                    fma2(acc[b][h], xp[b][0], w0);
                    fma2(acc[b][h], xp[b][1], w1);
                }
            }
        }
        float vals[32];
        #pragma unroll
        for (int b = 0; b < 4; b++)
            #pragma unroll
            for (int h = 0; h < HHn; h++) {
                float2 p = upk2(acc[b][h]);
                vals[b * 8 + h] = p.x + p.y;
            }
        #pragma unroll
        for (int s = 0; s < 5; s++) {
            const int n = 32 >> s;
            const int off = 1 << s;
            const bool up = (lane & off) != 0;
            #pragma unroll
            for (int i = 0; i < (n >> 1); i++) {
                float kept = up ? vals[i + (n >> 1)] : vals[i];
                float sent = up ? vals[i] : vals[i + (n >> 1)];
                float r = __shfl_xor_sync(0xffffffffu, sent, off);
                vals[i] = kept + r;
            }
        }
        logits[((size_t)(bs0 + jb) * HHn + jh) * LLn + l] = vals[0];
    }
}

// ---------------------------------------------------------------------------
// K2: fused softmax + ax. grid (bs=128, dhalf=2), block 256.
// ---------------------------------------------------------------------------
__global__ __launch_bounds__(256) void ax_kernel(
    const float* __restrict__ x, const float* __restrict__ logits,
    const int* __restrict__ mask, float* __restrict__ attn_out,
    __nv_bfloat16* __restrict__ axh, __nv_bfloat16* __restrict__ axl)
{
    __shared__ float  a_s[HHn][LLn];
    __shared__ __align__(8) float2 ap[LLn][HHn/2];
    const int bs = blockIdx.x, dh = blockIdx.y;
    const int tid = threadIdx.x, warp = tid >> 5, lane = tid & 31;

    {
        const int h = warp;
        const int row = bs * HHn + h;
        const float invT = 0.0441941738241592f;
        float v[4], mx = -3.4e38f;
        #pragma unroll
        for (int i = 0; i < 4; i++) {
            int l = lane + 32 * i;
            float lg = logits[(size_t)row * LLn + l] * invT;
            if (mask[bs * LLn + l] == 0) lg = -1e9f;
            v[i] = lg; mx = fmaxf(mx, lg);
        }
        #pragma unroll
        for (int off = 16; off; off >>= 1)
            mx = fmaxf(mx, __shfl_xor_sync(0xffffffffu, mx, off));
        float sum = 0.f;
        #pragma unroll
        for (int i = 0; i < 4; i++) { v[i] = __expf(v[i] - mx); sum += v[i]; }
        #pragma unroll
        for (int off = 16; off; off >>= 1)
            sum += __shfl_xor_sync(0xffffffffu, sum, off);
        float inv = 1.f / sum;
        #pragma unroll
        for (int i = 0; i < 4; i++) {
            int l = lane + 32 * i;
            float a = v[i] * inv;
            a_s[h][l] = a;
            if (dh == 0 && attn_out) attn_out[(size_t)row * LLn + l] = a;
        }
    }
    __syncthreads();

    #pragma unroll
    for (int i = tid; i < LLn * 4; i += 256) {
        int l = i >> 2, p = i & 3;
        ap[l][p] = make_float2(a_s[2 * p][l], a_s[2 * p + 1][l]);
    }
    __syncthreads();

    const int d = dh * 256 + tid;
    const float* xp = x + (size_t)bs * LLn * DDn + d;

    u64 acc[4];
    #pragma unroll
    for (int p = 0; p < 4; p++) acc[p] = 0ull;

    #pragma unroll 8
    for (int l = 0; l < LLn; l++) {
        float xv = xp[(size_t)l * DDn];
        u64 xx = pk2(xv, xv);
        #pragma unroll
        for (int p = 0; p < 4; p++) {
            u64 av = __double_as_longlong(*(const double*)&ap[l][p]);
            fma2(acc[p], av, xx);
        }
    }
    #pragma unroll
    for (int p = 0; p < 4; p++) {
        float2 s = upk2(acc[p]);
        size_t o0 = ((size_t)bs * HHn + 2 * p) * DDn + d;
        size_t o1 = ((size_t)bs * HHn + 2 * p + 1) * DDn + d;
        __nv_bfloat16 bh, bl;
        bsplit(s.x, bh, bl); axh[o0] = bh; axl[o0] = bl;
        bsplit(s.y, bh, bl); axh[o1] = bh; axl[o1] = bl;
    }
}

// ---------------------------------------------------------------------------
// Fused split: all three weight tensors fp32 -> (bf16 hi, bf16 lo)
// ---------------------------------------------------------------------------
__global__ __launch_bounds__(256) void split3_kernel(
    const float4* __restrict__ vw, const float4* __restrict__ w1,
    const float4* __restrict__ w2,
    __nv_bfloat16* __restrict__ vwh, __nv_bfloat16* __restrict__ vwl,
    __nv_bfloat16* __restrict__ w1h, __nv_bfloat16* __restrict__ w1l,
    __nv_bfloat16* __restrict__ w2h, __nv_bfloat16* __restrict__ w2l)
{
    constexpr int N0 = DDn * DDn / 4;
    constexpr int N1 = DIn * DDn / 4;
    int i = blockIdx.x * blockDim.x + threadIdx.x;
    const float4* in; __nv_bfloat16 *hi, *lo; int k;
    if (i < N0)            { in = vw; hi = vwh; lo = vwl; k = i; }
    else if (i < N0 + N1)  { in = w1; hi = w1h; lo = w1l; k = i - N0; }
    else                   { in = w2; hi = w2h; lo = w2l; k = i - N0 - N1; }
    float4 v = in[k];
    __nv_bfloat16 h[4], l[4];
    bsplit(v.x, h[0], l[0]); bsplit(v.y, h[1], l[1]);
    bsplit(v.z, h[2], l[2]); bsplit(v.w, h[3], l[3]);
    *(ushort4*)(hi + 4 * (size_t)k) = make_ushort4(
        __bfloat16_as_ushort(h[0]), __bfloat16_as_ushort(h[1]),
        __bfloat16_as_ushort(h[2]), __bfloat16_as_ushort(h[3]));
    *(ushort4*)(lo + 4 * (size_t)k) = make_ushort4(
        __bfloat16_as_ushort(l[0]), __bfloat16_as_ushort(l[1]),
        __bfloat16_as_ushort(l[2]), __bfloat16_as_ushort(l[3]));
}

// ---------------------------------------------------------------------------
// LayerNorm, warp per row (no block barriers). Reduces NPART partials.
// ---------------------------------------------------------------------------
template<int NPART, bool ADDBIAS, bool RES, bool SPLIT>
__global__ __launch_bounds__(256) void ln_kernel(
    const float* __restrict__ parts, const float* __restrict__ bias,
    const float* __restrict__ res,
    const float* __restrict__ g, const float* __restrict__ b,
    float* __restrict__ out,
    __nv_bfloat16* __restrict__ oh, __nv_bfloat16* __restrict__ ol)
{
    const int row = blockIdx.x * 8 + (threadIdx.x >> 5);
    const int lane = threadIdx.x & 31;
    const size_t base = (size_t)row * DDn + lane * 16;

    float v[16];
    #pragma unroll
    for (int q = 0; q < 4; q++) {
        float4 a = *(const float4*)(parts + base + q * 4);
        v[q*4+0] = a.x; v[q*4+1] = a.y; v[q*4+2] = a.z; v[q*4+3] = a.w;
    }
    #pragma unroll
    for (int p = 1; p < NPART; p++) {
        #pragma unroll
        for (int q = 0; q < 4; q++) {
            float4 a = *(const float4*)(parts + (size_t)p * NROW * DDn + base + q * 4);
            v[q*4+0] += a.x; v[q*4+1] += a.y; v[q*4+2] += a.z; v[q*4+3] += a.w;
        }
    }
    if (ADDBIAS) {
        #pragma unroll
        for (int q = 0; q < 4; q++) {
            float4 a = *(const float4*)(bias + lane * 16 + q * 4);
            v[q*4+0] += a.x; v[q*4+1] += a.y; v[q*4+2] += a.z; v[q*4+3] += a.w;
        }
    }
    if (RES) {
        #pragma unroll
        for (int q = 0; q < 4; q++) {
            float4 a = *(const float4*)(res + base + q * 4);
            v[q*4+0] += a.x; v[q*4+1] += a.y; v[q*4+2] += a.z; v[q*4+3] += a.w;
        }
    }

    float sum = 0.f;
    #pragma unroll
    for (int k = 0; k < 16; k++) sum += v[k];
    #pragma unroll
    for (int off = 16; off; off >>= 1)
        sum += __shfl_xor_sync(0xffffffffu, sum, off);
    float mu = sum * (1.f / DDn);

    float sq = 0.f;
    #pragma unroll
    for (int k = 0; k < 16; k++) { v[k] -= mu; sq += v[k] * v[k]; }
    #pragma unroll
    for (int off = 16; off; off >>= 1)
        sq += __shfl_xor_sync(0xffffffffu, sq, off);
    float inv = rsqrtf(sq * (1.f / DDn) + 1e-6f);

    float y[16];
    #pragma unroll
    for (int q = 0; q < 4; q++) {
        float4 gv = *(const float4*)(g + lane * 16 + q * 4);
        float4 bv = *(const float4*)(b + lane * 16 + q * 4);
        y[q*4+0] = v[q*4+0] * inv * gv.x + bv.x;
        y[q*4+1] = v[q*4+1] * inv * gv.y + bv.y;
        y[q*4+2] = v[q*4+2] * inv * gv.z + bv.z;
        y[q*4+3] = v[q*4+3] * inv * gv.w + bv.w;
    }
    if (out) {
        #pragma unroll
        for (int q = 0; q < 4; q++)
            *(float4*)(out + base + q * 4) =
                make_float4(y[q*4+0], y[q*4+1], y[q*4+2], y[q*4+3]);
    }
    if (SPLIT) {
        unsigned short hs[16], ls[16];
        #pragma unroll
        for (int k = 0; k < 16; k++) {
            __nv_bfloat16 h, l;
            bsplit(y[k], h, l);
            hs[k] = __bfloat16_as_ushort(h);
            ls[k] = __bfloat16_as_ushort(l);
        }
        *(uint4*)(oh + base)     = *(uint4*)&hs[0];
        *(uint4*)(oh + base + 8) = *(uint4*)&hs[8];
        *(uint4*)(ol + base)     = *(uint4*)&ls[0];
        *(uint4*)(ol + base + 8) = *(uint4*)&ls[8];
    }
}

// ---------------------------------------------------------------------------
extern "C" void kernel_launch(void* const* d_in, const int* in_sizes, int n_in,
                              void* d_out, int out_size)
{
    const float* x    = (const float*)d_in[0];
    const int*   mask = (const int*)  d_in[1];
    const float* w    = (const float*)d_in[2];
    const float* v_w  = (const float*)d_in[3];
    const float* ln_g = (const float*)d_in[4];
    const float* ln_b = (const float*)d_in[5];
    const float* w1   = (const float*)d_in[6];
    const float* b1   = (const float*)d_in[7];
    const float* w2   = (const float*)d_in[8];
    const float* b2   = (const float*)d_in[9];
    const float* fg   = (const float*)d_in[10];
    const float* fb   = (const float*)d_in[11];

    float *o, *lg, *pp;
    __nv_bfloat16 *axh, *axl, *oh, *ol, *hh, *hl;
    __nv_bfloat16 *vwh, *vwl, *w1h, *w1l, *w2h, *w2l;
    cudaGetSymbolAddress((void**)&o,   g_o);
    cudaGetSymbolAddress((void**)&lg,  g_logits);
    cudaGetSymbolAddress((void**)&pp,  g_p);
    cudaGetSymbolAddress((void**)&axh, g_axh);
    cudaGetSymbolAddress((void**)&axl, g_axl);
    cudaGetSymbolAddress((void**)&oh,  g_oh);
    cudaGetSymbolAddress((void**)&ol,  g_ol);
    cudaGetSymbolAddress((void**)&hh,  g_hh);
    cudaGetSymbolAddress((void**)&hl,  g_hl);
    cudaGetSymbolAddress((void**)&vwh, g_vwh);
    cudaGetSymbolAddress((void**)&vwl, g_vwl);
    cudaGetSymbolAddress((void**)&w1h, g_w1h);
    cudaGetSymbolAddress((void**)&w1l, g_w1l);
    cudaGetSymbolAddress((void**)&w2h, g_w2h);
    cudaGetSymbolAddress((void**)&w2l, g_w2l);

    float* y_out = (float*)d_out;
    float* attn_out = (out_size >= NROW * DDn + NROW * LLn)
                        ? (y_out + NROW * DDn) : nullptr;

    constexpr int SM64  = 2 * (2 * 64 * 128 + 2 * 64 * 128);    // 65536
    constexpr int SM128 = 2 * (2 * 64 * 128 + 2 * 128 * 128);   // 98304
    cudaFuncSetAttribute(gemm_mma<64, 64, 0>,
                         cudaFuncAttributeMaxDynamicSharedMemorySize, SM64);
    cudaFuncSetAttribute(gemm_mma<64, 128, 1>,
                         cudaFuncAttributeMaxDynamicSharedMemorySize, SM128);

    // fork split3 onto a side stream: overlaps logits+ax, joins before G0
    static cudaStream_t s2 = nullptr;
    static cudaEvent_t ev_fork = nullptr, ev_join = nullptr;
    if (s2 == nullptr) {
        cudaStreamCreateWithFlags(&s2, cudaStreamNonBlocking);
        cudaEventCreateWithFlags(&ev_fork, cudaEventDisableTiming);
        cudaEventCreateWithFlags(&ev_join, cudaEventDisableTiming);
    }
    constexpr int NSPLIT = (DDn*DDn + DIn*DDn + DDn*DIn) / 4;
    cudaEventRecord(ev_fork, 0);
    cudaStreamWaitEvent(s2, ev_fork, 0);
    split3_kernel<<<NSPLIT/256, 256, 0, s2>>>(
        (const float4*)v_w, (const float4*)w1, (const float4*)w2,
        vwh, vwl, w1h, w1l, w2h, w2l);
    cudaEventRecord(ev_join, s2);

    // attention: logits -> fused softmax + attn@x (main stream)
    logits_kernel<<<dim3(LLn, 2), 256>>>(x, w, lg);
    ax_kernel<<<dim3(NBS, 2), 256>>>(x, lg, mask, attn_out, axh, axl);

    cudaStreamWaitEvent(0, ev_join, 0);

    // G0: ax @ v_w^T, split-K2 -> p0,p1   (1024 x 512 x 512, KT=4)
    gemm_mma<64, 64, 0>
        <<<dim3(DDn/64, NROW/64, 2), 256, SM64>>>(
        axh, axl, vwh, vwl, nullptr, pp, nullptr, nullptr,
        NROW, DDn, DDn);

    // o = LN(p0+p1) (+ split)
    ln_kernel<2, false, false, true><<<NROW/8, 256>>>(
        pp, nullptr, nullptr, ln_g, ln_b, o, oh, ol);

    // G1: h = relu(o @ w1^T + b1)  (1024 x 2048 x 512, KT=8)
    gemm_mma<64, 128, 1>
        <<<dim3(DIn/128, NROW/64, 1), 256, SM128>>>(
        oh, ol, w1h, w1l, b1, nullptr, hh, hl,
        NROW, DIn, DDn);

    // G2: h @ w2^T, split-K4 -> p0..p3   (1024 x 512 x 2048, KT=8)
    gemm_mma<64, 64, 0>
        <<<dim3(DDn/64, NROW/64, 4), 256, SM64>>>(
        hh, hl, w2h, w2l, nullptr, pp, nullptr, nullptr,
        NROW, DDn, DIn);

    // y = LN(sum p + b2 + o)
    ln_kernel<4, true, true, false><<<NROW/8, 256>>>(
        pp, b2, o, fg, fb, y_out, nullptr, nullptr);
}

// round 12
// speedup vs baseline: 1.0390x; 1.0390x over previous
#include <cuda_runtime.h>
#include <cuda_bf16.h>
#include <cstdint>

#define HHn 8
#define LLn 128
#define DDn 512
#define DIn 2048
#define NBS 128
#define NROW 1024

typedef unsigned long long u64;

// ---------------- scratch (device globals; no allocation allowed) ----------
__device__ float g_o  [NROW*DDn];
__device__ float g_logits[NROW*LLn];
__device__ float g_p  [4][NROW*DDn];    // split-K partials
__device__ __nv_bfloat16 g_axh[NROW*DDn];
__device__ __nv_bfloat16 g_axl[NROW*DDn];
__device__ __nv_bfloat16 g_oh [NROW*DDn];
__device__ __nv_bfloat16 g_ol [NROW*DDn];
__device__ __nv_bfloat16 g_hh [NROW*DIn];
__device__ __nv_bfloat16 g_hl [NROW*DIn];
__device__ __nv_bfloat16 g_vwh[DDn*DDn];
__device__ __nv_bfloat16 g_vwl[DDn*DDn];
__device__ __nv_bfloat16 g_w1h[DIn*DDn];
__device__ __nv_bfloat16 g_w1l[DIn*DDn];
__device__ __nv_bfloat16 g_w2h[DDn*DIn];
__device__ __nv_bfloat16 g_w2l[DDn*DIn];

// ---------------- helpers ---------------------------------------------------
__device__ __forceinline__ uint32_t smem_u32(const void* p) {
    uint32_t a;
    asm("{ .reg .u64 t; cvta.to.shared.u64 t, %1; cvt.u32.u64 %0, t; }"
        : "=r"(a) : "l"(p));
    return a;
}
__device__ __forceinline__ void bsplit(float v, __nv_bfloat16& h, __nv_bfloat16& l) {
    h = __float2bfloat16(v);
    l = __float2bfloat16(v - __bfloat162float(h));
}
__device__ __forceinline__ void fma2(u64 &d, u64 a, u64 b) {
    asm("fma.rn.f32x2 %0, %1, %2, %0;" : "+l"(d) : "l"(a), "l"(b));
}
__device__ __forceinline__ u64 pk2(float a, float b) {
    u64 r; asm("mov.b64 %0, {%1,%2};" : "=l"(r) : "f"(a), "f"(b)); return r;
}
__device__ __forceinline__ float2 upk2(u64 v) {
    float2 r; asm("mov.b64 {%0,%1}, %2;" : "=f"(r.x), "=f"(r.y) : "l"(v)); return r;
}

#define CPA16(dst, src) \
    asm volatile("cp.async.cg.shared.global [%0], [%1], 16;" \
                 :: "r"(dst), "l"(src) : "memory")
#define CPA_COMMIT() asm volatile("cp.async.commit_group;" ::: "memory")
#define CPA_WAIT(n)  asm volatile("cp.async.wait_group %0;" :: "n"(n) : "memory")

#define LDSM4(r, addr) \
    asm volatile("ldmatrix.sync.aligned.m8n8.x4.shared.b16 {%0,%1,%2,%3}, [%4];" \
                 : "=r"((r)[0]), "=r"((r)[1]), "=r"((r)[2]), "=r"((r)[3]) \
                 : "r"(addr))

#define MMA_BF16(c, a, b) \
    asm volatile("mma.sync.aligned.m16n8k16.row.col.f32.bf16.bf16.f32 " \
        "{%0,%1,%2,%3}, {%4,%5,%6,%7}, {%8,%9}, {%0,%1,%2,%3};" \
        : "+f"((c)[0]), "+f"((c)[1]), "+f"((c)[2]), "+f"((c)[3]) \
        : "r"((a)[0]), "r"((a)[1]), "r"((a)[2]), "r"((a)[3]), \
          "r"((b)[0]), "r"((b)[1]))

// 64-byte smem rows (BK=32 bf16), 4 chunks of 16B, 2-bit XOR swizzle.
__device__ __forceinline__ uint32_t tile_off(int row, int chunk) {
    return (uint32_t)(row * 64 + ((chunk ^ ((row >> 1) & 3)) << 4));
}

// ---------------------------------------------------------------------------
// HMMA split-bf16 GEMM. BM=BN=128, BK=32, 4-stage pipeline, 256 threads.
// Warp tile 64x32 (WM=2, WN=4). Minimizes smem-fill traffic (the measured
// bottleneck): traffic = A*(N/128) + B*(M/128).
// EPI=0: fp32 partial store to C + z*M*N (split-K over blockIdx.z).
// EPI=1: bias + relu + bf16 hi/lo split store.
// ---------------------------------------------------------------------------
template<int EPI>
__global__ __launch_bounds__(256, 1) void gemm_mma(
    const __nv_bfloat16* __restrict__ Ah, const __nv_bfloat16* __restrict__ Al,
    const __nv_bfloat16* __restrict__ Bh, const __nv_bfloat16* __restrict__ Bl,
    const float* __restrict__ bias, float* __restrict__ C,
    __nv_bfloat16* __restrict__ Ch, __nv_bfloat16* __restrict__ Cl,
    int M, int N, int K)
{
    constexpr int BM = 128, BN = 128, BK = 32, STAGES = 4, THREADS = 256;
    constexpr int WM = 2, WN = 4;
    constexpr int A_BYTES = BM * 64;            // 8192
    constexpr int B_BYTES = BN * 64;
    constexpr int STAGE = 2 * A_BYTES + 2 * B_BYTES;   // 32768
    constexpr int MT = (BM / WM) / 16;          // 4
    constexpr int NT = (BN / WN) / 8;           // 4
    constexpr int CHUNKS = (2 * BM + 2 * BN) * 4;      // 2048
    constexpr int CPT = CHUNKS / THREADS;       // 8

    extern __shared__ __align__(128) char dsm[];
    const uint32_t sb = smem_u32(dsm);

    const int tid = threadIdx.x, wid = tid >> 5, lane = tid & 31;
    const int bm = blockIdx.y * BM, bn = blockIdx.x * BN;
    const int wm = wid / WN, wn = wid % WN;
    const int KT = (K / BK) / gridDim.z;
    const int kt0 = blockIdx.z * KT;

    auto load_stage = [&](int kt, int s) {
        const uint32_t base = sb + s * STAGE;
        const size_t gk = (size_t)(kt0 + kt) * BK;
        #pragma unroll
        for (int i = 0; i < CPT; i++) {
            int id = tid + i * THREADS;
            int row_all = id >> 2;
            int ck = id & 3;
            const __nv_bfloat16* g;
            uint32_t abase; int row; int rowbase;
            if (row_all < BM)            { g = Ah; abase = 0;                     row = row_all;            rowbase = bm; }
            else if (row_all < 2 * BM)   { g = Al; abase = A_BYTES;               row = row_all - BM;       rowbase = bm; }
            else if (row_all < 2*BM+BN)  { g = Bh; abase = 2 * A_BYTES;           row = row_all - 2 * BM;   rowbase = bn; }
            else                         { g = Bl; abase = 2 * A_BYTES + B_BYTES; row = row_all - 2*BM - BN; rowbase = bn; }
            const __nv_bfloat16* src =
                g + (size_t)(rowbase + row) * K + gk + ck * 8;
            CPA16(base + abase + tile_off(row, ck), src);
        }
        CPA_COMMIT();
    };

    float c[MT][NT][4];
    #pragma unroll
    for (int i = 0; i < MT; i++)
        #pragma unroll
        for (int j = 0; j < NT; j++)
            #pragma unroll
            for (int q = 0; q < 4; q++) c[i][j][q] = 0.f;

    // prologue: 3 stages in flight
    load_stage(0, 0);
    if (1 < KT) load_stage(1, 1);
    if (2 < KT) load_stage(2, 2);
    CPA_WAIT(2);
    __syncthreads();

    const int aRow0 = wm * (BM / WM);
    const int bRow0 = wn * (BN / WN);

    for (int kt = 0; kt < KT; kt++) {
        const uint32_t base = sb + (kt % STAGES) * STAGE;
        const uint32_t sAh = base;
        const uint32_t sAl = base + A_BYTES;
        const uint32_t sBh = base + 2 * A_BYTES;
        const uint32_t sBl = base + 2 * A_BYTES + B_BYTES;

        #pragma unroll
        for (int ks = 0; ks < 2; ks++) {
            uint32_t aH[MT][4], aL[MT][4];
            #pragma unroll
            for (int mt = 0; mt < MT; mt++) {
                int row = aRow0 + mt * 16 + (lane & 15);
                int ck = ks * 2 + (lane >> 4);
                uint32_t off = tile_off(row, ck);
                LDSM4(aH[mt], sAh + off);
                LDSM4(aL[mt], sAl + off);
            }
            uint32_t bH[NT][2], bL[NT][2];
            #pragma unroll
            for (int p = 0; p < NT / 2; p++) {
                int row = bRow0 + p * 16 + (lane & 7) + ((lane >> 4) << 3);
                int ck = ks * 2 + ((lane >> 3) & 1);
                uint32_t off = tile_off(row, ck);
                uint32_t r[4];
                LDSM4(r, sBh + off);
                bH[2*p][0] = r[0]; bH[2*p][1] = r[1];
                bH[2*p+1][0] = r[2]; bH[2*p+1][1] = r[3];
                LDSM4(r, sBl + off);
                bL[2*p][0] = r[0]; bL[2*p][1] = r[1];
                bL[2*p+1][0] = r[2]; bL[2*p+1][1] = r[3];
            }
            #pragma unroll
            for (int mt = 0; mt < MT; mt++)
                #pragma unroll
                for (int nt = 0; nt < NT; nt++) {
                    MMA_BF16(c[mt][nt], aH[mt], bH[nt]);
                    MMA_BF16(c[mt][nt], aH[mt], bL[nt]);
                    MMA_BF16(c[mt][nt], aL[mt], bH[nt]);
                }
        }

        if (kt + 3 < KT) {
            load_stage(kt + 3, (kt + 3) % STAGES);
            CPA_WAIT(2);
        } else {
            CPA_WAIT(0);
        }
        __syncthreads();
    }

    // ---- epilogue ----
    float* Cz = C + (size_t)blockIdx.z * M * N;
    #pragma unroll
    for (int mt = 0; mt < MT; mt++) {
        #pragma unroll
        for (int nt = 0; nt < NT; nt++) {
            int row = bm + aRow0 + mt * 16 + (lane >> 2);
            int col = bn + bRow0 + nt * 8 + ((lane & 3) << 1);
            #pragma unroll
            for (int half = 0; half < 2; half++) {
                int r = row + half * 8;
                float v0 = c[mt][nt][half * 2 + 0];
                float v1 = c[mt][nt][half * 2 + 1];
                if (EPI == 0) {
                    Cz[(size_t)r * N + col]     = v0;
                    Cz[(size_t)r * N + col + 1] = v1;
                } else {
                    v0 = fmaxf(v0 + bias[col], 0.f);
                    v1 = fmaxf(v1 + bias[col + 1], 0.f);
                    __nv_bfloat16 h, l;
                    bsplit(v0, h, l);
                    Ch[(size_t)r * N + col] = h; Cl[(size_t)r * N + col] = l;
                    bsplit(v1, h, l);
                    Ch[(size_t)r * N + col + 1] = h; Cl[(size_t)r * N + col + 1] = l;
                }
            }
        }
    }
}

// ---------------------------------------------------------------------------
// K1: logits[bs][h][l] = sum_d x[bs,l,d] * w[h,l,d].  grid (l=128, half=2).
// ---------------------------------------------------------------------------
__global__ __launch_bounds__(256) void logits_kernel(
    const float* __restrict__ x, const float* __restrict__ w,
    float* __restrict__ logits)
{
    __shared__ __align__(16) float w_s[HHn][DDn];
    const int l = blockIdx.x, half = blockIdx.y;
    const int tid = threadIdx.x, warp = tid >> 5, lane = tid & 31;

    #pragma unroll
    for (int i = 0; i < 4; i++) {
        int idx = tid + i * 256;
        int h = idx >> 7, d4 = idx & 127;
        ((float4*)w_s[h])[d4] =
            ((const float4*)(w + ((size_t)(h * LLn + l)) * DDn))[d4];
    }
    __syncthreads();

    const int j  = __brev((unsigned)lane) >> 27;
    const int jb = j >> 3, jh = j & 7;

    #pragma unroll
    for (int q = 0; q < 2; q++) {
        const int bs0 = half * 64 + warp * 8 + q * 4;
        u64 acc[4][HHn];
        #pragma unroll
        for (int b = 0; b < 4; b++)
            #pragma unroll
            for (int h = 0; h < HHn; h++) acc[b][h] = 0ull;

        #pragma unroll
        for (int c = 0; c < 4; c++) {
            const int d4 = c * 32 + lane;
            u64 xp[4][2];
            #pragma unroll
            for (int b = 0; b < 4; b++) {
                double2 xv = ((const double2*)
                    (x + ((size_t)((bs0 + b) * LLn + l)) * DDn))[d4];
                xp[b][0] = __double_as_longlong(xv.x);
                xp[b][1] = __double_as_longlong(xv.y);
            }
            #pragma unroll
            for (int h = 0; h < HHn; h++) {
                double2 wv = ((const double2*)w_s[h])[d4];
                u64 w0 = __double_as_longlong(wv.x);
                u64 w1 = __double_as_longlong(wv.y);
                #pragma unroll
                for (int b = 0; b < 4; b++) {
                    fma2(acc[b][h], xp[b][0], w0);
                    fma2(acc[b][h], xp[b][1], w1);
                }
            }
        }
        float vals[32];
        #pragma unroll
        for (int b = 0; b < 4; b++)
            #pragma unroll
            for (int h = 0; h < HHn; h++) {
                float2 p = upk2(acc[b][h]);
                vals[b * 8 + h] = p.x + p.y;
            }
        #pragma unroll
        for (int s = 0; s < 5; s++) {
            const int n = 32 >> s;
            const int off = 1 << s;
            const bool up = (lane & off) != 0;
            #pragma unroll
            for (int i = 0; i < (n >> 1); i++) {
                float kept = up ? vals[i + (n >> 1)] : vals[i];
                float sent = up ? vals[i] : vals[i + (n >> 1)];
                float r = __shfl_xor_sync(0xffffffffu, sent, off);
                vals[i] = kept + r;
            }
        }
        logits[((size_t)(bs0 + jb) * HHn + jh) * LLn + l] = vals[0];
    }
}

// ---------------------------------------------------------------------------
// K2: fused softmax + ax. grid (bs=128, dhalf=2), block 256.
// ---------------------------------------------------------------------------
__global__ __launch_bounds__(256) void ax_kernel(
    const float* __restrict__ x, const float* __restrict__ logits,
    const int* __restrict__ mask, float* __restrict__ attn_out,
    __nv_bfloat16* __restrict__ axh, __nv_bfloat16* __restrict__ axl)
{
    __shared__ float  a_s[HHn][LLn];
    __shared__ __align__(8) float2 ap[LLn][HHn/2];
    const int bs = blockIdx.x, dh = blockIdx.y;
    const int tid = threadIdx.x, warp = tid >> 5, lane = tid & 31;

    {
        const int h = warp;
        const int row = bs * HHn + h;
        const float invT = 0.0441941738241592f;
        float v[4], mx = -3.4e38f;
        #pragma unroll
        for (int i = 0; i < 4; i++) {
            int l = lane + 32 * i;
            float lg = logits[(size_t)row * LLn + l] * invT;
            if (mask[bs * LLn + l] == 0) lg = -1e9f;
            v[i] = lg; mx = fmaxf(mx, lg);
        }
        #pragma unroll
        for (int off = 16; off; off >>= 1)
            mx = fmaxf(mx, __shfl_xor_sync(0xffffffffu, mx, off));
        float sum = 0.f;
        #pragma unroll
        for (int i = 0; i < 4; i++) { v[i] = __expf(v[i] - mx); sum += v[i]; }
        #pragma unroll
        for (int off = 16; off; off >>= 1)
            sum += __shfl_xor_sync(0xffffffffu, sum, off);
        float inv = 1.f / sum;
        #pragma unroll
        for (int i = 0; i < 4; i++) {
            int l = lane + 32 * i;
            float a = v[i] * inv;
            a_s[h][l] = a;
            if (dh == 0 && attn_out) attn_out[(size_t)row * LLn + l] = a;
        }
    }
    __syncthreads();

    #pragma unroll
    for (int i = tid; i < LLn * 4; i += 256) {
        int l = i >> 2, p = i & 3;
        ap[l][p] = make_float2(a_s[2 * p][l], a_s[2 * p + 1][l]);
    }
    __syncthreads();

    const int d = dh * 256 + tid;
    const float* xp = x + (size_t)bs * LLn * DDn + d;

    u64 acc[4];
    #pragma unroll
    for (int p = 0; p < 4; p++) acc[p] = 0ull;

    #pragma unroll 8
    for (int l = 0; l < LLn; l++) {
        float xv = xp[(size_t)l * DDn];
        u64 xx = pk2(xv, xv);
        #pragma unroll
        for (int p = 0; p < 4; p++) {
            u64 av = __double_as_longlong(*(const double*)&ap[l][p]);
            fma2(acc[p], av, xx);
        }
    }
    #pragma unroll
    for (int p = 0; p < 4; p++) {
        float2 s = upk2(acc[p]);
        size_t o0 = ((size_t)bs * HHn + 2 * p) * DDn + d;
        size_t o1 = ((size_t)bs * HHn + 2 * p + 1) * DDn + d;
        __nv_bfloat16 bh, bl;
        bsplit(s.x, bh, bl); axh[o0] = bh; axl[o0] = bl;
        bsplit(s.y, bh, bl); axh[o1] = bh; axl[o1] = bl;
    }
}

// ---------------------------------------------------------------------------
// Fused split: all three weight tensors fp32 -> (bf16 hi, bf16 lo)
// ---------------------------------------------------------------------------
__global__ __launch_bounds__(256) void split3_kernel(
    const float4* __restrict__ vw, const float4* __restrict__ w1,
    const float4* __restrict__ w2,
    __nv_bfloat16* __restrict__ vwh, __nv_bfloat16* __restrict__ vwl,
    __nv_bfloat16* __restrict__ w1h, __nv_bfloat16* __restrict__ w1l,
    __nv_bfloat16* __restrict__ w2h, __nv_bfloat16* __restrict__ w2l)
{
    constexpr int N0 = DDn * DDn / 4;
    constexpr int N1 = DIn * DDn / 4;
    int i = blockIdx.x * blockDim.x + threadIdx.x;
    const float4* in; __nv_bfloat16 *hi, *lo; int k;
    if (i < N0)            { in = vw; hi = vwh; lo = vwl; k = i; }
    else if (i < N0 + N1)  { in = w1; hi = w1h; lo = w1l; k = i - N0; }
    else                   { in = w2; hi = w2h; lo = w2l; k = i - N0 - N1; }
    float4 v = in[k];
    __nv_bfloat16 h[4], l[4];
    bsplit(v.x, h[0], l[0]); bsplit(v.y, h[1], l[1]);
    bsplit(v.z, h[2], l[2]); bsplit(v.w, h[3], l[3]);
    *(ushort4*)(hi + 4 * (size_t)k) = make_ushort4(
        __bfloat16_as_ushort(h[0]), __bfloat16_as_ushort(h[1]),
        __bfloat16_as_ushort(h[2]), __bfloat16_as_ushort(h[3]));
    *(ushort4*)(lo + 4 * (size_t)k) = make_ushort4(
        __bfloat16_as_ushort(l[0]), __bfloat16_as_ushort(l[1]),
        __bfloat16_as_ushort(l[2]), __bfloat16_as_ushort(l[3]));
}

// ---------------------------------------------------------------------------
// LayerNorm, warp per row (no block barriers). Reduces NPART partials.
// ---------------------------------------------------------------------------
template<int NPART, bool ADDBIAS, bool RES, bool SPLIT>
__global__ __launch_bounds__(256) void ln_kernel(
    const float* __restrict__ parts, const float* __restrict__ bias,
    const float* __restrict__ res,
    const float* __restrict__ g, const float* __restrict__ b,
    float* __restrict__ out,
    __nv_bfloat16* __restrict__ oh, __nv_bfloat16* __restrict__ ol)
{
    const int row = blockIdx.x * 8 + (threadIdx.x >> 5);
    const int lane = threadIdx.x & 31;
    const size_t base = (size_t)row * DDn + lane * 16;

    float v[16];
    #pragma unroll
    for (int q = 0; q < 4; q++) {
        float4 a = *(const float4*)(parts + base + q * 4);
        v[q*4+0] = a.x; v[q*4+1] = a.y; v[q*4+2] = a.z; v[q*4+3] = a.w;
    }
    #pragma unroll
    for (int p = 1; p < NPART; p++) {
        #pragma unroll
        for (int q = 0; q < 4; q++) {
            float4 a = *(const float4*)(parts + (size_t)p * NROW * DDn + base + q * 4);
            v[q*4+0] += a.x; v[q*4+1] += a.y; v[q*4+2] += a.z; v[q*4+3] += a.w;
        }
    }
    if (ADDBIAS) {
        #pragma unroll
        for (int q = 0; q < 4; q++) {
            float4 a = *(const float4*)(bias + lane * 16 + q * 4);
            v[q*4+0] += a.x; v[q*4+1] += a.y; v[q*4+2] += a.z; v[q*4+3] += a.w;
        }
    }
    if (RES) {
        #pragma unroll
        for (int q = 0; q < 4; q++) {
            float4 a = *(const float4*)(res + base + q * 4);
            v[q*4+0] += a.x; v[q*4+1] += a.y; v[q*4+2] += a.z; v[q*4+3] += a.w;
        }
    }

    float sum = 0.f;
    #pragma unroll
    for (int k = 0; k < 16; k++) sum += v[k];
    #pragma unroll
    for (int off = 16; off; off >>= 1)
        sum += __shfl_xor_sync(0xffffffffu, sum, off);
    float mu = sum * (1.f / DDn);

    float sq = 0.f;
    #pragma unroll
    for (int k = 0; k < 16; k++) { v[k] -= mu; sq += v[k] * v[k]; }
    #pragma unroll
    for (int off = 16; off; off >>= 1)
        sq += __shfl_xor_sync(0xffffffffu, sq, off);
    float inv = rsqrtf(sq * (1.f / DDn) + 1e-6f);

    float y[16];
    #pragma unroll
    for (int q = 0; q < 4; q++) {
        float4 gv = *(const float4*)(g + lane * 16 + q * 4);
        float4 bv = *(const float4*)(b + lane * 16 + q * 4);
        y[q*4+0] = v[q*4+0] * inv * gv.x + bv.x;
        y[q*4+1] = v[q*4+1] * inv * gv.y + bv.y;
        y[q*4+2] = v[q*4+2] * inv * gv.z + bv.z;
        y[q*4+3] = v[q*4+3] * inv * gv.w + bv.w;
    }
    if (out) {
        #pragma unroll
        for (int q = 0; q < 4; q++)
            *(float4*)(out + base + q * 4) =
                make_float4(y[q*4+0], y[q*4+1], y[q*4+2], y[q*4+3]);
    }
    if (SPLIT) {
        unsigned short hs[16], ls[16];
        #pragma unroll
        for (int k = 0; k < 16; k++) {
            __nv_bfloat16 h, l;
            bsplit(y[k], h, l);
            hs[k] = __bfloat16_as_ushort(h);
            ls[k] = __bfloat16_as_ushort(l);
        }
        *(uint4*)(oh + base)     = *(uint4*)&hs[0];
        *(uint4*)(oh + base + 8) = *(uint4*)&hs[8];
        *(uint4*)(ol + base)     = *(uint4*)&ls[0];
        *(uint4*)(ol + base + 8) = *(uint4*)&ls[8];
    }
}

// ---------------------------------------------------------------------------
extern "C" void kernel_launch(void* const* d_in, const int* in_sizes, int n_in,
                              void* d_out, int out_size)
{
    const float* x    = (const float*)d_in[0];
    const int*   mask = (const int*)  d_in[1];
    const float* w    = (const float*)d_in[2];
    const float* v_w  = (const float*)d_in[3];
    const float* ln_g = (const float*)d_in[4];
    const float* ln_b = (const float*)d_in[5];
    const float* w1   = (const float*)d_in[6];
    const float* b1   = (const float*)d_in[7];
    const float* w2   = (const float*)d_in[8];
    const float* b2   = (const float*)d_in[9];
    const float* fg   = (const float*)d_in[10];
    const float* fb   = (const float*)d_in[11];

    float *o, *lg, *pp;
    __nv_bfloat16 *axh, *axl, *oh, *ol, *hh, *hl;
    __nv_bfloat16 *vwh, *vwl, *w1h, *w1l, *w2h, *w2l;
    cudaGetSymbolAddress((void**)&o,   g_o);
    cudaGetSymbolAddress((void**)&lg,  g_logits);
    cudaGetSymbolAddress((void**)&pp,  g_p);
    cudaGetSymbolAddress((void**)&axh, g_axh);
    cudaGetSymbolAddress((void**)&axl, g_axl);
    cudaGetSymbolAddress((void**)&oh,  g_oh);
    cudaGetSymbolAddress((void**)&ol,  g_ol);
    cudaGetSymbolAddress((void**)&hh,  g_hh);
    cudaGetSymbolAddress((void**)&hl,  g_hl);
    cudaGetSymbolAddress((void**)&vwh, g_vwh);
    cudaGetSymbolAddress((void**)&vwl, g_vwl);
    cudaGetSymbolAddress((void**)&w1h, g_w1h);
    cudaGetSymbolAddress((void**)&w1l, g_w1l);
    cudaGetSymbolAddress((void**)&w2h, g_w2h);
    cudaGetSymbolAddress((void**)&w2l, g_w2l);

    float* y_out = (float*)d_out;
    float* attn_out = (out_size >= NROW * DDn + NROW * LLn)
                        ? (y_out + NROW * DDn) : nullptr;

    constexpr int SMG = 4 * (2 * 128 * 64 + 2 * 128 * 64);   // 131072
    cudaFuncSetAttribute(gemm_mma<0>,
                         cudaFuncAttributeMaxDynamicSharedMemorySize, SMG);
    cudaFuncSetAttribute(gemm_mma<1>,
                         cudaFuncAttributeMaxDynamicSharedMemorySize, SMG);

    // all weight splits in one launch (main stream)
    constexpr int NSPLIT = (DDn*DDn + DIn*DDn + DDn*DIn) / 4;
    split3_kernel<<<NSPLIT/256, 256>>>(
        (const float4*)v_w, (const float4*)w1, (const float4*)w2,
        vwh, vwl, w1h, w1l, w2h, w2l);

    // attention: logits -> fused softmax + attn@x
    logits_kernel<<<dim3(LLn, 2), 256>>>(x, w, lg);
    ax_kernel<<<dim3(NBS, 2), 256>>>(x, lg, mask, attn_out, axh, axl);

    // G0: ax @ v_w^T, split-K4 -> p0..p3  (1024 x 512 x 512, KT=4)
    gemm_mma<0><<<dim3(DDn/128, NROW/128, 4), 256, SMG>>>(
        axh, axl, vwh, vwl, nullptr, pp, nullptr, nullptr,
        NROW, DDn, DDn);

    // o = LN(p0..p3) (+ split)
    ln_kernel<4, false, false, true><<<NROW/8, 256>>>(
        pp, nullptr, nullptr, ln_g, ln_b, o, oh, ol);

    // G1: h = relu(o @ w1^T + b1)  (1024 x 2048 x 512, KT=16)
    gemm_mma<1><<<dim3(DIn/128, NROW/128, 1), 256, SMG>>>(
        oh, ol, w1h, w1l, b1, nullptr, hh, hl,
        NROW, DIn, DDn);

    // G2: h @ w2^T, split-K4 -> p0..p3  (1024 x 512 x 2048, KT=16)
    gemm_mma<0><<<dim3(DDn/128, NROW/128, 4), 256, SMG>>>(
        hh, hl, w2h, w2l, nullptr, pp, nullptr, nullptr,
        NROW, DDn, DIn);

    // y = LN(sum p + b2 + o)
    ln_kernel<4, true, true, false><<<NROW/8, 256>>>(
        pp, b2, o, fg, fb, y_out, nullptr, nullptr);
}

// round 13
// speedup vs baseline: 1.1564x; 1.1130x over previous
#include <cuda_runtime.h>
#include <cuda_bf16.h>
#include <cuda_fp16.h>
#include <cstdint>

#define HHn 8
#define LLn 128
#define DDn 512
#define DIn 2048
#define NBS 128
#define NROW 1024

typedef unsigned long long u64;

// ---------------- scratch (device globals; no allocation allowed) ----------
__device__ float g_o  [NROW*DDn];
__device__ float g_logits[NROW*LLn];
__device__ float g_p  [4][NROW*DDn];    // split-K partials
__device__ __half g_axh[NROW*DDn];
__device__ __half g_axl[NROW*DDn];
__device__ __half g_oh [NROW*DDn];
__device__ __half g_ol [NROW*DDn];
__device__ __half g_hh [NROW*DIn];
__device__ __half g_hl [NROW*DIn];
__device__ __half g_vwf[DDn*DDn];
__device__ __half g_w1f[DIn*DDn];
__device__ __half g_w2f[DDn*DIn];

// ---------------- helpers ---------------------------------------------------
__device__ __forceinline__ uint32_t smem_u32(const void* p) {
    uint32_t a;
    asm("{ .reg .u64 t; cvta.to.shared.u64 t, %1; cvt.u32.u64 %0, t; }"
        : "=r"(a) : "l"(p));
    return a;
}
__device__ __forceinline__ void hsplit(float v, __half& h, __half& l) {
    h = __float2half(v);
    l = __float2half(v - __half2float(h));
}
__device__ __forceinline__ void fma2(u64 &d, u64 a, u64 b) {
    asm("fma.rn.f32x2 %0, %1, %2, %0;" : "+l"(d) : "l"(a), "l"(b));
}
__device__ __forceinline__ u64 pk2(float a, float b) {
    u64 r; asm("mov.b64 %0, {%1,%2};" : "=l"(r) : "f"(a), "f"(b)); return r;
}
__device__ __forceinline__ float2 upk2(u64 v) {
    float2 r; asm("mov.b64 {%0,%1}, %2;" : "=f"(r.x), "=f"(r.y) : "l"(v)); return r;
}

#define CPA16(dst, src) \
    asm volatile("cp.async.cg.shared.global [%0], [%1], 16;" \
                 :: "r"(dst), "l"(src) : "memory")
#define CPA_COMMIT() asm volatile("cp.async.commit_group;" ::: "memory")
#define CPA_WAIT(n)  asm volatile("cp.async.wait_group %0;" :: "n"(n) : "memory")

#define LDSM4(r, addr) \
    asm volatile("ldmatrix.sync.aligned.m8n8.x4.shared.b16 {%0,%1,%2,%3}, [%4];" \
                 : "=r"((r)[0]), "=r"((r)[1]), "=r"((r)[2]), "=r"((r)[3]) \
                 : "r"(addr))

#define MMA_F16(c, a, b) \
    asm volatile("mma.sync.aligned.m16n8k16.row.col.f32.f16.f16.f32 " \
        "{%0,%1,%2,%3}, {%4,%5,%6,%7}, {%8,%9}, {%0,%1,%2,%3};" \
        : "+f"((c)[0]), "+f"((c)[1]), "+f"((c)[2]), "+f"((c)[3]) \
        : "r"((a)[0]), "r"((a)[1]), "r"((a)[2]), "r"((a)[3]), \
          "r"((b)[0]), "r"((b)[1]))

// 64-byte smem rows (BK=32 fp16), 4 chunks of 16B, 2-bit XOR swizzle.
__device__ __forceinline__ uint32_t tile_off(int row, int chunk) {
    return (uint32_t)(row * 64 + ((chunk ^ ((row >> 1) & 3)) << 4));
}

// ---------------------------------------------------------------------------
// HMMA fp16 split-A GEMM: D = (Ah+Al) @ B16^T, 2 MMAs per tile step.
// BM=BN=128, BK=32, 4-stage pipeline, 256 threads, warp tile 64x32.
// EPI=0: fp32 partial store to C + z*M*N (split-K over blockIdx.z).
// EPI=1: bias + relu + fp16 hi/lo split store.
// ---------------------------------------------------------------------------
template<int EPI>
__global__ __launch_bounds__(256, 2) void gemm_mma(
    const __half* __restrict__ Ah, const __half* __restrict__ Al,
    const __half* __restrict__ Bf,
    const float* __restrict__ bias, float* __restrict__ C,
    __half* __restrict__ Ch, __half* __restrict__ Cl,
    int M, int N, int K)
{
    constexpr int BM = 128, BN = 128, BK = 32, STAGES = 4, THREADS = 256;
    constexpr int WM = 2, WN = 4;
    constexpr int A_BYTES = BM * 64;               // 8192
    constexpr int B_BYTES = BN * 64;               // 8192
    constexpr int STAGE = 2 * A_BYTES + B_BYTES;   // 24576
    constexpr int MT = (BM / WM) / 16;             // 4
    constexpr int NT = (BN / WN) / 8;              // 4
    constexpr int CHUNKS = (2 * BM + BN) * 4;      // 1536
    constexpr int CPT = CHUNKS / THREADS;          // 6

    extern __shared__ __align__(128) char dsm[];
    const uint32_t sb = smem_u32(dsm);

    const int tid = threadIdx.x, wid = tid >> 5, lane = tid & 31;
    const int bm = blockIdx.y * BM, bn = blockIdx.x * BN;
    const int wm = wid / WN, wn = wid % WN;
    const int KT = (K / BK) / gridDim.z;
    const int kt0 = blockIdx.z * KT;

    auto load_stage = [&](int kt, int s) {
        const uint32_t base = sb + s * STAGE;
        const size_t gk = (size_t)(kt0 + kt) * BK;
        #pragma unroll
        for (int i = 0; i < CPT; i++) {
            int id = tid + i * THREADS;
            int row_all = id >> 2;
            int ck = id & 3;
            const __half* g;
            uint32_t abase; int row; int rowbase;
            if (row_all < BM)          { g = Ah; abase = 0;           row = row_all;          rowbase = bm; }
            else if (row_all < 2 * BM) { g = Al; abase = A_BYTES;     row = row_all - BM;     rowbase = bm; }
            else                       { g = Bf; abase = 2 * A_BYTES; row = row_all - 2 * BM; rowbase = bn; }
            const __half* src =
                g + (size_t)(rowbase + row) * K + gk + ck * 8;
            CPA16(base + abase + tile_off(row, ck), src);
        }
        CPA_COMMIT();
    };

    float c[MT][NT][4];
    #pragma unroll
    for (int i = 0; i < MT; i++)
        #pragma unroll
        for (int j = 0; j < NT; j++)
            #pragma unroll
            for (int q = 0; q < 4; q++) c[i][j][q] = 0.f;

    load_stage(0, 0);
    if (1 < KT) load_stage(1, 1);
    if (2 < KT) load_stage(2, 2);
    CPA_WAIT(2);
    __syncthreads();

    const int aRow0 = wm * (BM / WM);
    const int bRow0 = wn * (BN / WN);

    for (int kt = 0; kt < KT; kt++) {
        const uint32_t base = sb + (kt % STAGES) * STAGE;
        const uint32_t sAh = base;
        const uint32_t sAl = base + A_BYTES;
        const uint32_t sB  = base + 2 * A_BYTES;

        #pragma unroll
        for (int ks = 0; ks < 2; ks++) {
            uint32_t aH[MT][4], aL[MT][4];
            #pragma unroll
            for (int mt = 0; mt < MT; mt++) {
                int row = aRow0 + mt * 16 + (lane & 15);
                int ck = ks * 2 + (lane >> 4);
                uint32_t off = tile_off(row, ck);
                LDSM4(aH[mt], sAh + off);
                LDSM4(aL[mt], sAl + off);
            }
            uint32_t bR[NT][2];
            #pragma unroll
            for (int p = 0; p < NT / 2; p++) {
                int row = bRow0 + p * 16 + (lane & 7) + ((lane >> 4) << 3);
                int ck = ks * 2 + ((lane >> 3) & 1);
                uint32_t r[4];
                LDSM4(r, sB + tile_off(row, ck));
                bR[2*p][0] = r[0]; bR[2*p][1] = r[1];
                bR[2*p+1][0] = r[2]; bR[2*p+1][1] = r[3];
            }
            #pragma unroll
            for (int mt = 0; mt < MT; mt++)
                #pragma unroll
                for (int nt = 0; nt < NT; nt++) {
                    MMA_F16(c[mt][nt], aH[mt], bR[nt]);
                    MMA_F16(c[mt][nt], aL[mt], bR[nt]);
                }
        }

        if (kt + 3 < KT) {
            load_stage(kt + 3, (kt + 3) % STAGES);
            CPA_WAIT(2);
        } else {
            CPA_WAIT(0);
        }
        __syncthreads();
    }

    // ---- epilogue ----
    float* Cz = C + (size_t)blockIdx.z * M * N;
    #pragma unroll
    for (int mt = 0; mt < MT; mt++) {
        #pragma unroll
        for (int nt = 0; nt < NT; nt++) {
            int row = bm + aRow0 + mt * 16 + (lane >> 2);
            int col = bn + bRow0 + nt * 8 + ((lane & 3) << 1);
            #pragma unroll
            for (int half = 0; half < 2; half++) {
                int r = row + half * 8;
                float v0 = c[mt][nt][half * 2 + 0];
                float v1 = c[mt][nt][half * 2 + 1];
                if (EPI == 0) {
                    Cz[(size_t)r * N + col]     = v0;
                    Cz[(size_t)r * N + col + 1] = v1;
                } else {
                    v0 = fmaxf(v0 + bias[col], 0.f);
                    v1 = fmaxf(v1 + bias[col + 1], 0.f);
                    __half h, l;
                    hsplit(v0, h, l);
                    Ch[(size_t)r * N + col] = h; Cl[(size_t)r * N + col] = l;
                    hsplit(v1, h, l);
                    Ch[(size_t)r * N + col + 1] = h; Cl[(size_t)r * N + col + 1] = l;
                }
            }
        }
    }
}

// ---------------------------------------------------------------------------
// K1 union: blocks [0,256) compute logits; blocks [256, 256+2304) convert the
// three weight tensors fp32 -> fp16 (overlapped in one launch).
// ---------------------------------------------------------------------------
__global__ __launch_bounds__(256) void logits_conv_kernel(
    const float* __restrict__ x, const float* __restrict__ w,
    float* __restrict__ logits,
    const float4* __restrict__ vw, const float4* __restrict__ w1,
    const float4* __restrict__ w2,
    __half* __restrict__ vwf, __half* __restrict__ w1f, __half* __restrict__ w2f)
{
    if (blockIdx.x >= 256) {
        constexpr int N0 = DDn * DDn / 4;
        constexpr int N1 = DIn * DDn / 4;
        int i = (blockIdx.x - 256) * 256 + threadIdx.x;
        const float4* in; __half* dst; int k;
        if (i < N0)            { in = vw; dst = vwf; k = i; }
        else if (i < N0 + N1)  { in = w1; dst = w1f; k = i - N0; }
        else                   { in = w2; dst = w2f; k = i - N0 - N1; }
        float4 v = in[k];
        ushort4 o4 = make_ushort4(
            __half_as_ushort(__float2half(v.x)),
            __half_as_ushort(__float2half(v.y)),
            __half_as_ushort(__float2half(v.z)),
            __half_as_ushort(__float2half(v.w)));
        *(ushort4*)(dst + 4 * (size_t)k) = o4;
        return;
    }

    __shared__ __align__(16) float w_s[HHn][DDn];
    const int l = blockIdx.x & 127, half = blockIdx.x >> 7;
    const int tid = threadIdx.x, warp = tid >> 5, lane = tid & 31;

    #pragma unroll
    for (int i = 0; i < 4; i++) {
        int idx = tid + i * 256;
        int h = idx >> 7, d4 = idx & 127;
        ((float4*)w_s[h])[d4] =
            ((const float4*)(w + ((size_t)(h * LLn + l)) * DDn))[d4];
    }
    __syncthreads();

    const int j  = __brev((unsigned)lane) >> 27;
    const int jb = j >> 3, jh = j & 7;

    #pragma unroll
    for (int q = 0; q < 2; q++) {
        const int bs0 = half * 64 + warp * 8 + q * 4;
        u64 acc[4][HHn];
        #pragma unroll
        for (int b = 0; b < 4; b++)
            #pragma unroll
            for (int h = 0; h < HHn; h++) acc[b][h] = 0ull;

        #pragma unroll
        for (int c = 0; c < 4; c++) {
            const int d4 = c * 32 + lane;
            u64 xp[4][2];
            #pragma unroll
            for (int b = 0; b < 4; b++) {
                double2 xv = ((const double2*)
                    (x + ((size_t)((bs0 + b) * LLn + l)) * DDn))[d4];
                xp[b][0] = __double_as_longlong(xv.x);
                xp[b][1] = __double_as_longlong(xv.y);
            }
            #pragma unroll
            for (int h = 0; h < HHn; h++) {
                double2 wv = ((const double2*)w_s[h])[d4];
                u64 w0 = __double_as_longlong(wv.x);
                u64 w1v = __double_as_longlong(wv.y);
                #pragma unroll
                for (int b = 0; b < 4; b++) {
                    fma2(acc[b][h], xp[b][0], w0);
                    fma2(acc[b][h], xp[b][1], w1v);
                }
            }
        }
        float vals[32];
        #pragma unroll
        for (int b = 0; b < 4; b++)
            #pragma unroll
            for (int h = 0; h < HHn; h++) {
                float2 p = upk2(acc[b][h]);
                vals[b * 8 + h] = p.x + p.y;
            }
        #pragma unroll
        for (int s = 0; s < 5; s++) {
            const int n = 32 >> s;
            const int off = 1 << s;
            const bool up = (lane & off) != 0;
            #pragma unroll
            for (int i = 0; i < (n >> 1); i++) {
                float kept = up ? vals[i + (n >> 1)] : vals[i];
                float sent = up ? vals[i] : vals[i + (n >> 1)];
                float r = __shfl_xor_sync(0xffffffffu, sent, off);
                vals[i] = kept + r;
            }
        }
        logits[((size_t)(bs0 + jb) * HHn + jh) * LLn + l] = vals[0];
    }
}

// ---------------------------------------------------------------------------
// K2: fused softmax + ax. grid (bs=128, dhalf=2), block 256. fp16 split out.
// ---------------------------------------------------------------------------
__global__ __launch_bounds__(256) void ax_kernel(
    const float* __restrict__ x, const float* __restrict__ logits,
    const int* __restrict__ mask, float* __restrict__ attn_out,
    __half* __restrict__ axh, __half* __restrict__ axl)
{
    __shared__ float  a_s[HHn][LLn];
    __shared__ __align__(8) float2 ap[LLn][HHn/2];
    const int bs = blockIdx.x, dh = blockIdx.y;
    const int tid = threadIdx.x, warp = tid >> 5, lane = tid & 31;

    {
        const int h = warp;
        const int row = bs * HHn + h;
        const float invT = 0.0441941738241592f;
        float v[4], mx = -3.4e38f;
        #pragma unroll
        for (int i = 0; i < 4; i++) {
            int l = lane + 32 * i;
            float lg = logits[(size_t)row * LLn + l] * invT;
            if (mask[bs * LLn + l] == 0) lg = -1e9f;
            v[i] = lg; mx = fmaxf(mx, lg);
        }
        #pragma unroll
        for (int off = 16; off; off >>= 1)
            mx = fmaxf(mx, __shfl_xor_sync(0xffffffffu, mx, off));
        float sum = 0.f;
        #pragma unroll
        for (int i = 0; i < 4; i++) { v[i] = __expf(v[i] - mx); sum += v[i]; }
        #pragma unroll
        for (int off = 16; off; off >>= 1)
            sum += __shfl_xor_sync(0xffffffffu, sum, off);
        float inv = 1.f / sum;
        #pragma unroll
        for (int i = 0; i < 4; i++) {
            int l = lane + 32 * i;
            float a = v[i] * inv;
            a_s[h][l] = a;
            if (dh == 0 && attn_out) attn_out[(size_t)row * LLn + l] = a;
        }
    }
    __syncthreads();

    #pragma unroll
    for (int i = tid; i < LLn * 4; i += 256) {
        int l = i >> 2, p = i & 3;
        ap[l][p] = make_float2(a_s[2 * p][l], a_s[2 * p + 1][l]);
    }
    __syncthreads();

    const int d = dh * 256 + tid;
    const float* xp = x + (size_t)bs * LLn * DDn + d;

    u64 acc[4];
    #pragma unroll
    for (int p = 0; p < 4; p++) acc[p] = 0ull;

    #pragma unroll 8
    for (int l = 0; l < LLn; l++) {
        float xv = xp[(size_t)l * DDn];
        u64 xx = pk2(xv, xv);
        #pragma unroll
        for (int p = 0; p < 4; p++) {
            u64 av = __double_as_longlong(*(const double*)&ap[l][p]);
            fma2(acc[p], av, xx);
        }
    }
    #pragma unroll
    for (int p = 0; p < 4; p++) {
        float2 s = upk2(acc[p]);
        size_t o0 = ((size_t)bs * HHn + 2 * p) * DDn + d;
        size_t o1 = ((size_t)bs * HHn + 2 * p + 1) * DDn + d;
        __half hh, hl;
        hsplit(s.x, hh, hl); axh[o0] = hh; axl[o0] = hl;
        hsplit(s.y, hh, hl); axh[o1] = hh; axl[o1] = hl;
    }
}

// ---------------------------------------------------------------------------
// LayerNorm, warp per row (no block barriers). Reduces NPART partials.
// ---------------------------------------------------------------------------
template<int NPART, bool ADDBIAS, bool RES, bool SPLIT>
__global__ __launch_bounds__(256) void ln_kernel(
    const float* __restrict__ parts, const float* __restrict__ bias,
    const float* __restrict__ res,
    const float* __restrict__ g, const float* __restrict__ b,
    float* __restrict__ out,
    __half* __restrict__ oh, __half* __restrict__ ol)
{
    const int row = blockIdx.x * 8 + (threadIdx.x >> 5);
    const int lane = threadIdx.x & 31;
    const size_t base = (size_t)row * DDn + lane * 16;

    float v[16];
    #pragma unroll
    for (int q = 0; q < 4; q++) {
        float4 a = *(const float4*)(parts + base + q * 4);
        v[q*4+0] = a.x; v[q*4+1] = a.y; v[q*4+2] = a.z; v[q*4+3] = a.w;
    }
    #pragma unroll
    for (int p = 1; p < NPART; p++) {
        #pragma unroll
        for (int q = 0; q < 4; q++) {
            float4 a = *(const float4*)(parts + (size_t)p * NROW * DDn + base + q * 4);
            v[q*4+0] += a.x; v[q*4+1] += a.y; v[q*4+2] += a.z; v[q*4+3] += a.w;
        }
    }
    if (ADDBIAS) {
        #pragma unroll
        for (int q = 0; q < 4; q++) {
            float4 a = *(const float4*)(bias + lane * 16 + q * 4);
            v[q*4+0] += a.x; v[q*4+1] += a.y; v[q*4+2] += a.z; v[q*4+3] += a.w;
        }
    }
    if (RES) {
        #pragma unroll
        for (int q = 0; q < 4; q++) {
            float4 a = *(const float4*)(res + base + q * 4);
            v[q*4+0] += a.x; v[q*4+1] += a.y; v[q*4+2] += a.z; v[q*4+3] += a.w;
        }
    }

    float sum = 0.f;
    #pragma unroll
    for (int k = 0; k < 16; k++) sum += v[k];
    #pragma unroll
    for (int off = 16; off; off >>= 1)
        sum += __shfl_xor_sync(0xffffffffu, sum, off);
    float mu = sum * (1.f / DDn);

    float sq = 0.f;
    #pragma unroll
    for (int k = 0; k < 16; k++) { v[k] -= mu; sq += v[k] * v[k]; }
    #pragma unroll
    for (int off = 16; off; off >>= 1)
        sq += __shfl_xor_sync(0xffffffffu, sq, off);
    float inv = rsqrtf(sq * (1.f / DDn) + 1e-6f);

    float y[16];
    #pragma unroll
    for (int q = 0; q < 4; q++) {
        float4 gv = *(const float4*)(g + lane * 16 + q * 4);
        float4 bv = *(const float4*)(b + lane * 16 + q * 4);
        y[q*4+0] = v[q*4+0] * inv * gv.x + bv.x;
        y[q*4+1] = v[q*4+1] * inv * gv.y + bv.y;
        y[q*4+2] = v[q*4+2] * inv * gv.z + bv.z;
        y[q*4+3] = v[q*4+3] * inv * gv.w + bv.w;
    }
    if (out) {
        #pragma unroll
        for (int q = 0; q < 4; q++)
            *(float4*)(out + base + q * 4) =
                make_float4(y[q*4+0], y[q*4+1], y[q*4+2], y[q*4+3]);
    }
    if (SPLIT) {
        unsigned short hs[16], ls[16];
        #pragma unroll
        for (int k = 0; k < 16; k++) {
            __half h, l;
            hsplit(y[k], h, l);
            hs[k] = __half_as_ushort(h);
            ls[k] = __half_as_ushort(l);
        }
        *(uint4*)(oh + base)     = *(uint4*)&hs[0];
        *(uint4*)(oh + base + 8) = *(uint4*)&hs[8];
        *(uint4*)(ol + base)     = *(uint4*)&ls[0];
        *(uint4*)(ol + base + 8) = *(uint4*)&ls[8];
    }
}

// ---------------------------------------------------------------------------
extern "C" void kernel_launch(void* const* d_in, const int* in_sizes, int n_in,
                              void* d_out, int out_size)
{
    const float* x    = (const float*)d_in[0];
    const int*   mask = (const int*)  d_in[1];
    const float* w    = (const float*)d_in[2];
    const float* v_w  = (const float*)d_in[3];
    const float* ln_g = (const float*)d_in[4];
    const float* ln_b = (const float*)d_in[5];
    const float* w1   = (const float*)d_in[6];
    const float* b1   = (const float*)d_in[7];
    const float* w2   = (const float*)d_in[8];
    const float* b2   = (const float*)d_in[9];
    const float* fg   = (const float*)d_in[10];
    const float* fb   = (const float*)d_in[11];

    float *o, *lg, *pp;
    __half *axh, *axl, *oh, *ol, *hh, *hl, *vwf, *w1f, *w2f;
    cudaGetSymbolAddress((void**)&o,   g_o);
    cudaGetSymbolAddress((void**)&lg,  g_logits);
    cudaGetSymbolAddress((void**)&pp,  g_p);
    cudaGetSymbolAddress((void**)&axh, g_axh);
    cudaGetSymbolAddress((void**)&axl, g_axl);
    cudaGetSymbolAddress((void**)&oh,  g_oh);
    cudaGetSymbolAddress((void**)&ol,  g_ol);
    cudaGetSymbolAddress((void**)&hh,  g_hh);
    cudaGetSymbolAddress((void**)&hl,  g_hl);
    cudaGetSymbolAddress((void**)&vwf, g_vwf);
    cudaGetSymbolAddress((void**)&w1f, g_w1f);
    cudaGetSymbolAddress((void**)&w2f, g_w2f);

    float* y_out = (float*)d_out;
    float* attn_out = (out_size >= NROW * DDn + NROW * LLn)
                        ? (y_out + NROW * DDn) : nullptr;

    constexpr int SMG = 4 * (2 * 128 * 64 + 128 * 64);   // 98304
    cudaFuncSetAttribute(gemm_mma<0>,
                         cudaFuncAttributeMaxDynamicSharedMemorySize, SMG);
    cudaFuncSetAttribute(gemm_mma<1>,
                         cudaFuncAttributeMaxDynamicSharedMemorySize, SMG);

    // K1 union: logits (256 blocks) + weight fp32->fp16 conversion (2304)
    constexpr int NCONV = (DDn*DDn + DIn*DDn + DDn*DIn) / 4 / 256;  // 2304
    logits_conv_kernel<<<256 + NCONV, 256>>>(
        x, w, lg, (const float4*)v_w, (const float4*)w1, (const float4*)w2,
        vwf, w1f, w2f);

    // K2: fused softmax + attn@x (fp16 split out)
    ax_kernel<<<dim3(NBS, 2), 256>>>(x, lg, mask, attn_out, axh, axl);

    // G0: ax @ v_w^T, split-K4 -> p0..p3  (1024 x 512 x 512, KT=4)
    gemm_mma<0><<<dim3(DDn/128, NROW/128, 4), 256, SMG>>>(
        axh, axl, vwf, nullptr, pp, nullptr, nullptr,
        NROW, DDn, DDn);

    // o = LN(p0..p3) (+ fp16 split)
    ln_kernel<4, false, false, true><<<NROW/8, 256>>>(
        pp, nullptr, nullptr, ln_g, ln_b, o, oh, ol);

    // G1: h = relu(o @ w1^T + b1)  (1024 x 2048 x 512, KT=16)
    gemm_mma<1><<<dim3(DIn/128, NROW/128, 1), 256, SMG>>>(
        oh, ol, w1f, b1, nullptr, hh, hl,
        NROW, DIn, DDn);

    // G2: h @ w2^T, split-K4 -> p0..p3  (1024 x 512 x 2048, KT=16)
    gemm_mma<0><<<dim3(DDn/128, NROW/128, 4), 256, SMG>>>(
        hh, hl, w2f, nullptr, pp, nullptr, nullptr,
        NROW, DDn, DIn);

    // y = LN(sum p + b2 + o)
    ln_kernel<4, true, true, false><<<NROW/8, 256>>>(
        pp, b2, o, fg, fb, y_out, nullptr, nullptr);
}

// round 14
// speedup vs baseline: 1.3526x; 1.1697x over previous
#include <cuda_runtime.h>
#include <cuda_fp16.h>
#include <cstdint>

#define HHn 8
#define LLn 128
#define DDn 512
#define DIn 2048
#define NBS 128
#define NROW 1024

typedef unsigned long long u64;

// ---------------- scratch (device globals; no allocation allowed) ----------
__device__ float g_o  [NROW*DDn];
__device__ float g_logits[NROW*LLn];
__device__ float g_p  [4][NROW*DDn];    // split-K partials
__device__ __half g_axh[NROW*DDn];
__device__ __half g_axl[NROW*DDn];
__device__ __half g_oh [NROW*DDn];
__device__ __half g_ol [NROW*DDn];
__device__ __half g_hh [NROW*DIn];
__device__ __half g_vwf[DDn*DDn];
__device__ __half g_w1f[DIn*DDn];
__device__ __half g_w2f[DDn*DIn];

// ---------------- helpers ---------------------------------------------------
__device__ __forceinline__ uint32_t smem_u32(const void* p) {
    uint32_t a;
    asm("{ .reg .u64 t; cvta.to.shared.u64 t, %1; cvt.u32.u64 %0, t; }"
        : "=r"(a) : "l"(p));
    return a;
}
__device__ __forceinline__ void hsplit(float v, __half& h, __half& l) {
    h = __float2half(v);
    l = __float2half(v - __half2float(h));
}
__device__ __forceinline__ void fma2(u64 &d, u64 a, u64 b) {
    asm("fma.rn.f32x2 %0, %1, %2, %0;" : "+l"(d) : "l"(a), "l"(b));
}
__device__ __forceinline__ u64 pk2(float a, float b) {
    u64 r; asm("mov.b64 %0, {%1,%2};" : "=l"(r) : "f"(a), "f"(b)); return r;
}
__device__ __forceinline__ float2 upk2(u64 v) {
    float2 r; asm("mov.b64 {%0,%1}, %2;" : "=f"(r.x), "=f"(r.y) : "l"(v)); return r;
}

#define CPA16(dst, src) \
    asm volatile("cp.async.cg.shared.global [%0], [%1], 16;" \
                 :: "r"(dst), "l"(src) : "memory")
#define CPA_COMMIT() asm volatile("cp.async.commit_group;" ::: "memory")
#define CPA_WAIT(n)  asm volatile("cp.async.wait_group %0;" :: "n"(n) : "memory")

#define LDSM4(r, addr) \
    asm volatile("ldmatrix.sync.aligned.m8n8.x4.shared.b16 {%0,%1,%2,%3}, [%4];" \
                 : "=r"((r)[0]), "=r"((r)[1]), "=r"((r)[2]), "=r"((r)[3]) \
                 : "r"(addr))

#define MMA_F16(c, a, b) \
    asm volatile("mma.sync.aligned.m16n8k16.row.col.f32.f16.f16.f32 " \
        "{%0,%1,%2,%3}, {%4,%5,%6,%7}, {%8,%9}, {%0,%1,%2,%3};" \
        : "+f"((c)[0]), "+f"((c)[1]), "+f"((c)[2]), "+f"((c)[3]) \
        : "r"((a)[0]), "r"((a)[1]), "r"((a)[2]), "r"((a)[3]), \
          "r"((b)[0]), "r"((b)[1]))

// 64-byte smem rows (BK=32 fp16), 4 chunks of 16B, 2-bit XOR swizzle.
__device__ __forceinline__ uint32_t tile_off(int row, int chunk) {
    return (uint32_t)(row * 64 + ((chunk ^ ((row >> 1) & 3)) << 4));
}

// ---------------------------------------------------------------------------
// HMMA fp16 GEMM. ASPLIT=1: A = Ah+Al (2 MMAs); ASPLIT=0: A = Ah (1 MMA).
// BM=BN=128, BK=32, 4-stage pipeline, 256 threads, warp tile 64x32.
// EPI=0: fp32 partial store to C + z*M*N (split-K over blockIdx.z).
// EPI=1: bias + relu + single fp16 store to Ch.
// ---------------------------------------------------------------------------
template<int ASPLIT, int EPI>
__global__ __launch_bounds__(256, 2) void gemm_mma(
    const __half* __restrict__ Ah, const __half* __restrict__ Al,
    const __half* __restrict__ Bf,
    const float* __restrict__ bias, float* __restrict__ C,
    __half* __restrict__ Ch,
    int M, int N, int K)
{
    constexpr int BM = 128, BN = 128, BK = 32, STAGES = 4, THREADS = 256;
    constexpr int WM = 2, WN = 4;
    constexpr int NA = 1 + ASPLIT;
    constexpr int A_BYTES = BM * 64;
    constexpr int B_BYTES = BN * 64;
    constexpr int STAGE = NA * A_BYTES + B_BYTES;
    constexpr int MT = (BM / WM) / 16;             // 4
    constexpr int NT = (BN / WN) / 8;              // 4
    constexpr int CHUNKS = (NA * BM + BN) * 4;
    constexpr int CPT = CHUNKS / THREADS;

    extern __shared__ __align__(128) char dsm[];
    const uint32_t sb = smem_u32(dsm);

    const int tid = threadIdx.x, wid = tid >> 5, lane = tid & 31;
    const int bm = blockIdx.y * BM, bn = blockIdx.x * BN;
    const int wm = wid / WN, wn = wid % WN;
    const int KT = (K / BK) / gridDim.z;
    const int kt0 = blockIdx.z * KT;

    auto load_stage = [&](int kt, int s) {
        const uint32_t base = sb + s * STAGE;
        const size_t gk = (size_t)(kt0 + kt) * BK;
        #pragma unroll
        for (int i = 0; i < CPT; i++) {
            int id = tid + i * THREADS;
            int row_all = id >> 2;
            int ck = id & 3;
            const __half* g;
            uint32_t abase; int row; int rowbase;
            if (row_all < BM) {
                g = Ah; abase = 0; row = row_all; rowbase = bm;
            } else if (ASPLIT && row_all < 2 * BM) {
                g = Al; abase = A_BYTES; row = row_all - BM; rowbase = bm;
            } else {
                g = Bf; abase = NA * A_BYTES; row = row_all - NA * BM; rowbase = bn;
            }
            const __half* src =
                g + (size_t)(rowbase + row) * K + gk + ck * 8;
            CPA16(base + abase + tile_off(row, ck), src);
        }
        CPA_COMMIT();
    };

    float c[MT][NT][4];
    #pragma unroll
    for (int i = 0; i < MT; i++)
        #pragma unroll
        for (int j = 0; j < NT; j++)
            #pragma unroll
            for (int q = 0; q < 4; q++) c[i][j][q] = 0.f;

    load_stage(0, 0);
    if (1 < KT) load_stage(1, 1);
    if (2 < KT) load_stage(2, 2);
    CPA_WAIT(2);
    __syncthreads();

    const int aRow0 = wm * (BM / WM);
    const int bRow0 = wn * (BN / WN);

    for (int kt = 0; kt < KT; kt++) {
        const uint32_t base = sb + (kt % STAGES) * STAGE;
        const uint32_t sAh = base;
        const uint32_t sAl = base + A_BYTES;
        const uint32_t sB  = base + NA * A_BYTES;

        #pragma unroll
        for (int ks = 0; ks < 2; ks++) {
            uint32_t aH[MT][4], aL[MT][4];
            #pragma unroll
            for (int mt = 0; mt < MT; mt++) {
                int row = aRow0 + mt * 16 + (lane & 15);
                int ck = ks * 2 + (lane >> 4);
                uint32_t off = tile_off(row, ck);
                LDSM4(aH[mt], sAh + off);
                if (ASPLIT) LDSM4(aL[mt], sAl + off);
            }
            uint32_t bR[NT][2];
            #pragma unroll
            for (int p = 0; p < NT / 2; p++) {
                int row = bRow0 + p * 16 + (lane & 7) + ((lane >> 4) << 3);
                int ck = ks * 2 + ((lane >> 3) & 1);
                uint32_t r[4];
                LDSM4(r, sB + tile_off(row, ck));
                bR[2*p][0] = r[0]; bR[2*p][1] = r[1];
                bR[2*p+1][0] = r[2]; bR[2*p+1][1] = r[3];
            }
            #pragma unroll
            for (int mt = 0; mt < MT; mt++)
                #pragma unroll
                for (int nt = 0; nt < NT; nt++) {
                    MMA_F16(c[mt][nt], aH[mt], bR[nt]);
                    if (ASPLIT) MMA_F16(c[mt][nt], aL[mt], bR[nt]);
                }
        }

        if (kt + 3 < KT) {
            load_stage(kt + 3, (kt + 3) % STAGES);
            CPA_WAIT(2);
        } else {
            CPA_WAIT(0);
        }
        __syncthreads();
    }

    // ---- epilogue ----
    float* Cz = C + (size_t)blockIdx.z * M * N;
    #pragma unroll
    for (int mt = 0; mt < MT; mt++) {
        #pragma unroll
        for (int nt = 0; nt < NT; nt++) {
            int row = bm + aRow0 + mt * 16 + (lane >> 2);
            int col = bn + bRow0 + nt * 8 + ((lane & 3) << 1);
            #pragma unroll
            for (int half = 0; half < 2; half++) {
                int r = row + half * 8;
                float v0 = c[mt][nt][half * 2 + 0];
                float v1 = c[mt][nt][half * 2 + 1];
                if (EPI == 0) {
                    Cz[(size_t)r * N + col]     = v0;
                    Cz[(size_t)r * N + col + 1] = v1;
                } else {
                    v0 = fmaxf(v0 + bias[col], 0.f);
                    v1 = fmaxf(v1 + bias[col + 1], 0.f);
                    Ch[(size_t)r * N + col]     = __float2half(v0);
                    Ch[(size_t)r * N + col + 1] = __float2half(v1);
                }
            }
        }
    }
}

// ---------------------------------------------------------------------------
// K1 union: blocks [0,256) compute logits; blocks [256, 256+2304) convert the
// three weight tensors fp32 -> fp16 (overlapped in one launch).
// ---------------------------------------------------------------------------
__global__ __launch_bounds__(256) void logits_conv_kernel(
    const float* __restrict__ x, const float* __restrict__ w,
    float* __restrict__ logits,
    const float4* __restrict__ vw, const float4* __restrict__ w1,
    const float4* __restrict__ w2,
    __half* __restrict__ vwf, __half* __restrict__ w1f, __half* __restrict__ w2f)
{
    if (blockIdx.x >= 256) {
        constexpr int N0 = DDn * DDn / 4;
        constexpr int N1 = DIn * DDn / 4;
        int i = (blockIdx.x - 256) * 256 + threadIdx.x;
        const float4* in; __half* dst; int k;
        if (i < N0)            { in = vw; dst = vwf; k = i; }
        else if (i < N0 + N1)  { in = w1; dst = w1f; k = i - N0; }
        else                   { in = w2; dst = w2f; k = i - N0 - N1; }
        float4 v = in[k];
        ushort4 o4 = make_ushort4(
            __half_as_ushort(__float2half(v.x)),
            __half_as_ushort(__float2half(v.y)),
            __half_as_ushort(__float2half(v.z)),
            __half_as_ushort(__float2half(v.w)));
        *(ushort4*)(dst + 4 * (size_t)k) = o4;
        return;
    }

    __shared__ __align__(16) float w_s[HHn][DDn];
    const int l = blockIdx.x & 127, half = blockIdx.x >> 7;
    const int tid = threadIdx.x, warp = tid >> 5, lane = tid & 31;

    #pragma unroll
    for (int i = 0; i < 4; i++) {
        int idx = tid + i * 256;
        int h = idx >> 7, d4 = idx & 127;
        ((float4*)w_s[h])[d4] =
            ((const float4*)(w + ((size_t)(h * LLn + l)) * DDn))[d4];
    }
    __syncthreads();

    const int j  = __brev((unsigned)lane) >> 27;
    const int jb = j >> 3, jh = j & 7;

    #pragma unroll
    for (int q = 0; q < 2; q++) {
        const int bs0 = half * 64 + warp * 8 + q * 4;
        u64 acc[4][HHn];
        #pragma unroll
        for (int b = 0; b < 4; b++)
            #pragma unroll
            for (int h = 0; h < HHn; h++) acc[b][h] = 0ull;

        #pragma unroll
        for (int c = 0; c < 4; c++) {
            const int d4 = c * 32 + lane;
            u64 xp[4][2];
            #pragma unroll
            for (int b = 0; b < 4; b++) {
                double2 xv = ((const double2*)
                    (x + ((size_t)((bs0 + b) * LLn + l)) * DDn))[d4];
                xp[b][0] = __double_as_longlong(xv.x);
                xp[b][1] = __double_as_longlong(xv.y);
            }
            #pragma unroll
            for (int h = 0; h < HHn; h++) {
                double2 wv = ((const double2*)w_s[h])[d4];
                u64 w0 = __double_as_longlong(wv.x);
                u64 w1v = __double_as_longlong(wv.y);
                #pragma unroll
                for (int b = 0; b < 4; b++) {
                    fma2(acc[b][h], xp[b][0], w0);
                    fma2(acc[b][h], xp[b][1], w1v);
                }
            }
        }
        float vals[32];
        #pragma unroll
        for (int b = 0; b < 4; b++)
            #pragma unroll
            for (int h = 0; h < HHn; h++) {
                float2 p = upk2(acc[b][h]);
                vals[b * 8 + h] = p.x + p.y;
            }
        #pragma unroll
        for (int s = 0; s < 5; s++) {
            const int n = 32 >> s;
            const int off = 1 << s;
            const bool up = (lane & off) != 0;
            #pragma unroll
            for (int i = 0; i < (n >> 1); i++) {
                float kept = up ? vals[i + (n >> 1)] : vals[i];
                float sent = up ? vals[i] : vals[i + (n >> 1)];
                float r = __shfl_xor_sync(0xffffffffu, sent, off);
                vals[i] = kept + r;
            }
        }
        logits[((size_t)(bs0 + jb) * HHn + jh) * LLn + l] = vals[0];
    }
}

// ---------------------------------------------------------------------------
// K2: fused softmax + ax. grid (bs=128, dhalf=2), block 256. fp16 split out.
// ---------------------------------------------------------------------------
__global__ __launch_bounds__(256) void ax_kernel(
    const float* __restrict__ x, const float* __restrict__ logits,
    const int* __restrict__ mask, float* __restrict__ attn_out,
    __half* __restrict__ axh, __half* __restrict__ axl)
{
    __shared__ float  a_s[HHn][LLn];
    __shared__ __align__(8) float2 ap[LLn][HHn/2];
    const int bs = blockIdx.x, dh = blockIdx.y;
    const int tid = threadIdx.x, warp = tid >> 5, lane = tid & 31;

    {
        const int h = warp;
        const int row = bs * HHn + h;
        const float invT = 0.0441941738241592f;
        float v[4], mx = -3.4e38f;
        #pragma unroll
        for (int i = 0; i < 4; i++) {
            int l = lane + 32 * i;
            float lg = logits[(size_t)row * LLn + l] * invT;
            if (mask[bs * LLn + l] == 0) lg = -1e9f;
            v[i] = lg; mx = fmaxf(mx, lg);
        }
        #pragma unroll
        for (int off = 16; off; off >>= 1)
            mx = fmaxf(mx, __shfl_xor_sync(0xffffffffu, mx, off));
        float sum = 0.f;
        #pragma unroll
        for (int i = 0; i < 4; i++) { v[i] = __expf(v[i] - mx); sum += v[i]; }
        #pragma unroll
        for (int off = 16; off; off >>= 1)
            sum += __shfl_xor_sync(0xffffffffu, sum, off);
        float inv = 1.f / sum;
        #pragma unroll
        for (int i = 0; i < 4; i++) {
            int l = lane + 32 * i;
            float a = v[i] * inv;
            a_s[h][l] = a;
            if (dh == 0 && attn_out) attn_out[(size_t)row * LLn + l] = a;
        }
    }
    __syncthreads();

    #pragma unroll
    for (int i = tid; i < LLn * 4; i += 256) {
        int l = i >> 2, p = i & 3;
        ap[l][p] = make_float2(a_s[2 * p][l], a_s[2 * p + 1][l]);
    }
    __syncthreads();

    const int d = dh * 256 + tid;
    const float* xp = x + (size_t)bs * LLn * DDn + d;

    u64 acc[4];
    #pragma unroll
    for (int p = 0; p < 4; p++) acc[p] = 0ull;

    #pragma unroll 8
    for (int l = 0; l < LLn; l++) {
        float xv = xp[(size_t)l * DDn];
        u64 xx = pk2(xv, xv);
        #pragma unroll
        for (int p = 0; p < 4; p++) {
            u64 av = __double_as_longlong(*(const double*)&ap[l][p]);
            fma2(acc[p], av, xx);
        }
    }
    #pragma unroll
    for (int p = 0; p < 4; p++) {
        float2 s = upk2(acc[p]);
        size_t o0 = ((size_t)bs * HHn + 2 * p) * DDn + d;
        size_t o1 = ((size_t)bs * HHn + 2 * p + 1) * DDn + d;
        __half hh, hl;
        hsplit(s.x, hh, hl); axh[o0] = hh; axl[o0] = hl;
        hsplit(s.y, hh, hl); axh[o1] = hh; axl[o1] = hl;
    }
}

// ---------------------------------------------------------------------------
// LayerNorm, 2 warps per row (single-pass mean/var, one cheap block sync).
// grid NROW/4, block 256 (8 warps = 4 rows). Reduces NPART partials.
// ---------------------------------------------------------------------------
template<int NPART, bool ADDBIAS, bool RES, bool SPLIT>
__global__ __launch_bounds__(256) void ln_kernel(
    const float* __restrict__ parts, const float* __restrict__ bias,
    const float* __restrict__ res,
    const float* __restrict__ g, const float* __restrict__ b,
    float* __restrict__ out,
    __half* __restrict__ oh, __half* __restrict__ ol)
{
    __shared__ float red[8][2];
    const int warp = threadIdx.x >> 5, lane = threadIdx.x & 31;
    const int wp = warp >> 1, hf = warp & 1;
    const int row = blockIdx.x * 4 + wp;
    const int off = hf * 256 + lane * 8;
    const size_t base = (size_t)row * DDn + off;

    float v[8];
    #pragma unroll
    for (int q = 0; q < 2; q++) {
        float4 a = *(const float4*)(parts + base + q * 4);
        v[q*4+0] = a.x; v[q*4+1] = a.y; v[q*4+2] = a.z; v[q*4+3] = a.w;
    }
    #pragma unroll
    for (int p = 1; p < NPART; p++) {
        #pragma unroll
        for (int q = 0; q < 2; q++) {
            float4 a = *(const float4*)(parts + (size_t)p * NROW * DDn + base + q * 4);
            v[q*4+0] += a.x; v[q*4+1] += a.y; v[q*4+2] += a.z; v[q*4+3] += a.w;
        }
    }
    if (ADDBIAS) {
        #pragma unroll
        for (int q = 0; q < 2; q++) {
            float4 a = *(const float4*)(bias + off + q * 4);
            v[q*4+0] += a.x; v[q*4+1] += a.y; v[q*4+2] += a.z; v[q*4+3] += a.w;
        }
    }
    if (RES) {
        #pragma unroll
        for (int q = 0; q < 2; q++) {
            float4 a = *(const float4*)(res + base + q * 4);
            v[q*4+0] += a.x; v[q*4+1] += a.y; v[q*4+2] += a.z; v[q*4+3] += a.w;
        }
    }

    float s = 0.f, sq = 0.f;
    #pragma unroll
    for (int k = 0; k < 8; k++) { s += v[k]; sq += v[k] * v[k]; }
    #pragma unroll
    for (int o2 = 16; o2; o2 >>= 1) {
        s  += __shfl_xor_sync(0xffffffffu, s,  o2);
        sq += __shfl_xor_sync(0xffffffffu, sq, o2);
    }
    if (lane == 0) { red[warp][0] = s; red[warp][1] = sq; }
    __syncthreads();
    float ts = red[wp * 2][0] + red[wp * 2 + 1][0];
    float tq = red[wp * 2][1] + red[wp * 2 + 1][1];
    float mu  = ts * (1.f / DDn);
    float var = tq * (1.f / DDn) - mu * mu;
    float inv = rsqrtf(var + 1e-6f);

    float y[8];
    #pragma unroll
    for (int q = 0; q < 2; q++) {
        float4 gv = *(const float4*)(g + off + q * 4);
        float4 bv = *(const float4*)(b + off + q * 4);
        y[q*4+0] = (v[q*4+0] - mu) * inv * gv.x + bv.x;
        y[q*4+1] = (v[q*4+1] - mu) * inv * gv.y + bv.y;
        y[q*4+2] = (v[q*4+2] - mu) * inv * gv.z + bv.z;
        y[q*4+3] = (v[q*4+3] - mu) * inv * gv.w + bv.w;
    }
    if (out) {
        #pragma unroll
        for (int q = 0; q < 2; q++)
            *(float4*)(out + base + q * 4) =
                make_float4(y[q*4+0], y[q*4+1], y[q*4+2], y[q*4+3]);
    }
    if (SPLIT) {
        unsigned short hs[8], ls[8];
        #pragma unroll
        for (int k = 0; k < 8; k++) {
            __half h, l;
            hsplit(y[k], h, l);
            hs[k] = __half_as_ushort(h);
            ls[k] = __half_as_ushort(l);
        }
        *(uint4*)(oh + base) = *(uint4*)&hs[0];
        *(uint4*)(ol + base) = *(uint4*)&ls[0];
    }
}

// ---------------------------------------------------------------------------
extern "C" void kernel_launch(void* const* d_in, const int* in_sizes, int n_in,
                              void* d_out, int out_size)
{
    const float* x    = (const float*)d_in[0];
    const int*   mask = (const int*)  d_in[1];
    const float* w    = (const float*)d_in[2];
    const float* v_w  = (const float*)d_in[3];
    const float* ln_g = (const float*)d_in[4];
    const float* ln_b = (const float*)d_in[5];
    const float* w1   = (const float*)d_in[6];
    const float* b1   = (const float*)d_in[7];
    const float* w2   = (const float*)d_in[8];
    const float* b2   = (const float*)d_in[9];
    const float* fg   = (const float*)d_in[10];
    const float* fb   = (const float*)d_in[11];

    float *o, *lg, *pp;
    __half *axh, *axl, *oh, *ol, *hh, *vwf, *w1f, *w2f;
    cudaGetSymbolAddress((void**)&o,   g_o);
    cudaGetSymbolAddress((void**)&lg,  g_logits);
    cudaGetSymbolAddress((void**)&pp,  g_p);
    cudaGetSymbolAddress((void**)&axh, g_axh);
    cudaGetSymbolAddress((void**)&axl, g_axl);
    cudaGetSymbolAddress((void**)&oh,  g_oh);
    cudaGetSymbolAddress((void**)&ol,  g_ol);
    cudaGetSymbolAddress((void**)&hh,  g_hh);
    cudaGetSymbolAddress((void**)&vwf, g_vwf);
    cudaGetSymbolAddress((void**)&w1f, g_w1f);
    cudaGetSymbolAddress((void**)&w2f, g_w2f);

    float* y_out = (float*)d_out;
    float* attn_out = (out_size >= NROW * DDn + NROW * LLn)
                        ? (y_out + NROW * DDn) : nullptr;

    constexpr int SMG2 = 4 * (2 * 128 * 64 + 128 * 64);   // 98304 (ASPLIT=1)
    constexpr int SMG1 = 4 * (128 * 64 + 128 * 64);       // 65536 (ASPLIT=0)
    cudaFuncSetAttribute(gemm_mma<1, 0>,
                         cudaFuncAttributeMaxDynamicSharedMemorySize, SMG2);
    cudaFuncSetAttribute(gemm_mma<1, 1>,
                         cudaFuncAttributeMaxDynamicSharedMemorySize, SMG2);
    cudaFuncSetAttribute(gemm_mma<0, 0>,
                         cudaFuncAttributeMaxDynamicSharedMemorySize, SMG1);

    // K1 union: logits (256 blocks) + weight fp32->fp16 conversion (2304)
    constexpr int NCONV = (DDn*DDn + DIn*DDn + DDn*DIn) / 4 / 256;  // 2304
    logits_conv_kernel<<<256 + NCONV, 256>>>(
        x, w, lg, (const float4*)v_w, (const float4*)w1, (const float4*)w2,
        vwf, w1f, w2f);

    // K2: fused softmax + attn@x (fp16 split out)
    ax_kernel<<<dim3(NBS, 2), 256>>>(x, lg, mask, attn_out, axh, axl);

    // G0: (axh+axl) @ vwf^T, split-K4 -> p0..p3  (1024 x 512 x 512, KT=4)
    gemm_mma<1, 0><<<dim3(DDn/128, NROW/128, 4), 256, SMG2>>>(
        axh, axl, vwf, nullptr, pp, nullptr,
        NROW, DDn, DDn);

    // o = LN(p0..p3) (+ fp16 split)
    ln_kernel<4, false, false, true><<<NROW/4, 256>>>(
        pp, nullptr, nullptr, ln_g, ln_b, o, oh, ol);

    // G1: hh = fp16(relu((oh+ol) @ w1f^T + b1))  (1024 x 2048 x 512, KT=16)
    gemm_mma<1, 1><<<dim3(DIn/128, NROW/128, 1), 256, SMG2>>>(
        oh, ol, w1f, b1, nullptr, hh,
        NROW, DIn, DDn);

    // G2: hh @ w2f^T, single-MMA, split-K4 -> p0..p3 (1024 x 512 x 2048)
    gemm_mma<0, 0><<<dim3(DDn/128, NROW/128, 4), 256, SMG1>>>(
        hh, nullptr, w2f, nullptr, pp, nullptr,
        NROW, DDn, DIn);

    // y = LN(sum p + b2 + o)
    ln_kernel<4, true, true, false><<<NROW/4, 256>>>(
        pp, b2, o, fg, fb, y_out, nullptr, nullptr);
}

// round 15
// speedup vs baseline: 1.4780x; 1.0927x over previous
#include <cuda_runtime.h>
#include <cuda_fp16.h>
#include <cstdint>

#define HHn 8
#define LLn 128
#define DDn 512
#define DIn 2048
#define NBS 128
#define NROW 1024

typedef unsigned long long u64;

// ---------------- scratch (device globals; no allocation allowed) ----------
__device__ float g_o  [NROW*DDn];
__device__ float g_logits[NROW*LLn];
__device__ float g_p  [4][NROW*DDn];    // split-K partials
__device__ __half g_axh[NROW*DDn];
__device__ __half g_axl[NROW*DDn];
__device__ __half g_oh [NROW*DDn];
__device__ __half g_hh [NROW*DIn];
__device__ __half g_vwf[DDn*DDn];
__device__ __half g_w1f[DIn*DDn];
__device__ __half g_w2f[DDn*DIn];

// ---------------- helpers ---------------------------------------------------
__device__ __forceinline__ uint32_t smem_u32(const void* p) {
    uint32_t a;
    asm("{ .reg .u64 t; cvta.to.shared.u64 t, %1; cvt.u32.u64 %0, t; }"
        : "=r"(a) : "l"(p));
    return a;
}
__device__ __forceinline__ void hsplit(float v, __half& h, __half& l) {
    h = __float2half(v);
    l = __float2half(v - __half2float(h));
}
__device__ __forceinline__ void fma2(u64 &d, u64 a, u64 b) {
    asm("fma.rn.f32x2 %0, %1, %2, %0;" : "+l"(d) : "l"(a), "l"(b));
}
__device__ __forceinline__ u64 pk2(float a, float b) {
    u64 r; asm("mov.b64 %0, {%1,%2};" : "=l"(r) : "f"(a), "f"(b)); return r;
}
__device__ __forceinline__ float2 upk2(u64 v) {
    float2 r; asm("mov.b64 {%0,%1}, %2;" : "=f"(r.x), "=f"(r.y) : "l"(v)); return r;
}

#define CPA16(dst, src) \
    asm volatile("cp.async.cg.shared.global [%0], [%1], 16;" \
                 :: "r"(dst), "l"(src) : "memory")
#define CPA_COMMIT() asm volatile("cp.async.commit_group;" ::: "memory")
#define CPA_WAIT(n)  asm volatile("cp.async.wait_group %0;" :: "n"(n) : "memory")

#define LDSM4(r, addr) \
    asm volatile("ldmatrix.sync.aligned.m8n8.x4.shared.b16 {%0,%1,%2,%3}, [%4];" \
                 : "=r"((r)[0]), "=r"((r)[1]), "=r"((r)[2]), "=r"((r)[3]) \
                 : "r"(addr))

#define MMA_F16(c, a, b) \
    asm volatile("mma.sync.aligned.m16n8k16.row.col.f32.f16.f16.f32 " \
        "{%0,%1,%2,%3}, {%4,%5,%6,%7}, {%8,%9}, {%0,%1,%2,%3};" \
        : "+f"((c)[0]), "+f"((c)[1]), "+f"((c)[2]), "+f"((c)[3]) \
        : "r"((a)[0]), "r"((a)[1]), "r"((a)[2]), "r"((a)[3]), \
          "r"((b)[0]), "r"((b)[1]))

// 64-byte smem rows (BK=32 fp16), 4 chunks of 16B, 2-bit XOR swizzle.
__device__ __forceinline__ uint32_t tile_off(int row, int chunk) {
    return (uint32_t)(row * 64 + ((chunk ^ ((row >> 1) & 3)) << 4));
}

// ---------------------------------------------------------------------------
// HMMA fp16 GEMM. ASPLIT=1: A = Ah+Al (2 MMAs); ASPLIT=0: A = Ah (1 MMA).
// BM=BN=128, BK=32, 4-stage pipeline, 256 threads, warp tile 64x32.
// EPI=0: fp32 partial store to C + z*M*N (split-K over blockIdx.z).
// EPI=1: bias + relu + single fp16 store to Ch.
// ---------------------------------------------------------------------------
template<int ASPLIT, int EPI>
__global__ __launch_bounds__(256, 2) void gemm_mma(
    const __half* __restrict__ Ah, const __half* __restrict__ Al,
    const __half* __restrict__ Bf,
    const float* __restrict__ bias, float* __restrict__ C,
    __half* __restrict__ Ch,
    int M, int N, int K)
{
    constexpr int BM = 128, BN = 128, BK = 32, STAGES = 4, THREADS = 256;
    constexpr int WM = 2, WN = 4;
    constexpr int NA = 1 + ASPLIT;
    constexpr int A_BYTES = BM * 64;
    constexpr int B_BYTES = BN * 64;
    constexpr int STAGE = NA * A_BYTES + B_BYTES;
    constexpr int MT = (BM / WM) / 16;             // 4
    constexpr int NT = (BN / WN) / 8;              // 4
    constexpr int CHUNKS = (NA * BM + BN) * 4;
    constexpr int CPT = CHUNKS / THREADS;

    extern __shared__ __align__(128) char dsm[];
    const uint32_t sb = smem_u32(dsm);

    const int tid = threadIdx.x, wid = tid >> 5, lane = tid & 31;
    const int bm = blockIdx.y * BM, bn = blockIdx.x * BN;
    const int wm = wid / WN, wn = wid % WN;
    const int KT = (K / BK) / gridDim.z;
    const int kt0 = blockIdx.z * KT;

    auto load_stage = [&](int kt, int s) {
        const uint32_t base = sb + s * STAGE;
        const size_t gk = (size_t)(kt0 + kt) * BK;
        #pragma unroll
        for (int i = 0; i < CPT; i++) {
            int id = tid + i * THREADS;
            int row_all = id >> 2;
            int ck = id & 3;
            const __half* g;
            uint32_t abase; int row; int rowbase;
            if (row_all < BM) {
                g = Ah; abase = 0; row = row_all; rowbase = bm;
            } else if (ASPLIT && row_all < 2 * BM) {
                g = Al; abase = A_BYTES; row = row_all - BM; rowbase = bm;
            } else {
                g = Bf; abase = NA * A_BYTES; row = row_all - NA * BM; rowbase = bn;
            }
            const __half* src =
                g + (size_t)(rowbase + row) * K + gk + ck * 8;
            CPA16(base + abase + tile_off(row, ck), src);
        }
        CPA_COMMIT();
    };

    float c[MT][NT][4];
    #pragma unroll
    for (int i = 0; i < MT; i++)
        #pragma unroll
        for (int j = 0; j < NT; j++)
            #pragma unroll
            for (int q = 0; q < 4; q++) c[i][j][q] = 0.f;

    load_stage(0, 0);
    if (1 < KT) load_stage(1, 1);
    if (2 < KT) load_stage(2, 2);
    CPA_WAIT(2);
    __syncthreads();

    const int aRow0 = wm * (BM / WM);
    const int bRow0 = wn * (BN / WN);

    for (int kt = 0; kt < KT; kt++) {
        const uint32_t base = sb + (kt % STAGES) * STAGE;
        const uint32_t sAh = base;
        const uint32_t sAl = base + A_BYTES;
        const uint32_t sB  = base + NA * A_BYTES;

        #pragma unroll
        for (int ks = 0; ks < 2; ks++) {
            uint32_t aH[MT][4], aL[MT][4];
            #pragma unroll
            for (int mt = 0; mt < MT; mt++) {
                int row = aRow0 + mt * 16 + (lane & 15);
                int ck = ks * 2 + (lane >> 4);
                uint32_t off = tile_off(row, ck);
                LDSM4(aH[mt], sAh + off);
                if (ASPLIT) LDSM4(aL[mt], sAl + off);
            }
            uint32_t bR[NT][2];
            #pragma unroll
            for (int p = 0; p < NT / 2; p++) {
                int row = bRow0 + p * 16 + (lane & 7) + ((lane >> 4) << 3);
                int ck = ks * 2 + ((lane >> 3) & 1);
                uint32_t r[4];
                LDSM4(r, sB + tile_off(row, ck));
                bR[2*p][0] = r[0]; bR[2*p][1] = r[1];
                bR[2*p+1][0] = r[2]; bR[2*p+1][1] = r[3];
            }
            #pragma unroll
            for (int mt = 0; mt < MT; mt++)
                #pragma unroll
                for (int nt = 0; nt < NT; nt++) {
                    MMA_F16(c[mt][nt], aH[mt], bR[nt]);
                    if (ASPLIT) MMA_F16(c[mt][nt], aL[mt], bR[nt]);
                }
        }

        if (kt + 3 < KT) {
            load_stage(kt + 3, (kt + 3) % STAGES);
            CPA_WAIT(2);
        } else {
            CPA_WAIT(0);
        }
        __syncthreads();
    }

    // ---- epilogue ----
    float* Cz = C + (size_t)blockIdx.z * M * N;
    #pragma unroll
    for (int mt = 0; mt < MT; mt++) {
        #pragma unroll
        for (int nt = 0; nt < NT; nt++) {
            int row = bm + aRow0 + mt * 16 + (lane >> 2);
            int col = bn + bRow0 + nt * 8 + ((lane & 3) << 1);
            #pragma unroll
            for (int half = 0; half < 2; half++) {
                int r = row + half * 8;
                float v0 = c[mt][nt][half * 2 + 0];
                float v1 = c[mt][nt][half * 2 + 1];
                if (EPI == 0) {
                    Cz[(size_t)r * N + col]     = v0;
                    Cz[(size_t)r * N + col + 1] = v1;
                } else {
                    v0 = fmaxf(v0 + bias[col], 0.f);
                    v1 = fmaxf(v1 + bias[col + 1], 0.f);
                    Ch[(size_t)r * N + col]     = __float2half(v0);
                    Ch[(size_t)r * N + col + 1] = __float2half(v1);
                }
            }
        }
    }
}

// ---------------------------------------------------------------------------
// K1 union: blocks [0,256) compute logits; blocks [256, 256+2304) convert the
// three weight tensors fp32 -> fp16 (overlapped in one launch).
// ---------------------------------------------------------------------------
__global__ __launch_bounds__(256) void logits_conv_kernel(
    const float* __restrict__ x, const float* __restrict__ w,
    float* __restrict__ logits,
    const float4* __restrict__ vw, const float4* __restrict__ w1,
    const float4* __restrict__ w2,
    __half* __restrict__ vwf, __half* __restrict__ w1f, __half* __restrict__ w2f)
{
    if (blockIdx.x >= 256) {
        constexpr int N0 = DDn * DDn / 4;
        constexpr int N1 = DIn * DDn / 4;
        int i = (blockIdx.x - 256) * 256 + threadIdx.x;
        const float4* in; __half* dst; int k;
        if (i < N0)            { in = vw; dst = vwf; k = i; }
        else if (i < N0 + N1)  { in = w1; dst = w1f; k = i - N0; }
        else                   { in = w2; dst = w2f; k = i - N0 - N1; }
        float4 v = in[k];
        ushort4 o4 = make_ushort4(
            __half_as_ushort(__float2half(v.x)),
            __half_as_ushort(__float2half(v.y)),
            __half_as_ushort(__float2half(v.z)),
            __half_as_ushort(__float2half(v.w)));
        *(ushort4*)(dst + 4 * (size_t)k) = o4;
        return;
    }

    __shared__ __align__(16) float w_s[HHn][DDn];
    const int l = blockIdx.x & 127, half = blockIdx.x >> 7;
    const int tid = threadIdx.x, warp = tid >> 5, lane = tid & 31;

    #pragma unroll
    for (int i = 0; i < 4; i++) {
        int idx = tid + i * 256;
        int h = idx >> 7, d4 = idx & 127;
        ((float4*)w_s[h])[d4] =
            ((const float4*)(w + ((size_t)(h * LLn + l)) * DDn))[d4];
    }
    __syncthreads();

    const int j  = __brev((unsigned)lane) >> 27;
    const int jb = j >> 3, jh = j & 7;

    #pragma unroll
    for (int q = 0; q < 2; q++) {
        const int bs0 = half * 64 + warp * 8 + q * 4;
        u64 acc[4][HHn];
        #pragma unroll
        for (int b = 0; b < 4; b++)
            #pragma unroll
            for (int h = 0; h < HHn; h++) acc[b][h] = 0ull;

        #pragma unroll
        for (int c = 0; c < 4; c++) {
            const int d4 = c * 32 + lane;
            u64 xp[4][2];
            #pragma unroll
            for (int b = 0; b < 4; b++) {
                double2 xv = ((const double2*)
                    (x + ((size_t)((bs0 + b) * LLn + l)) * DDn))[d4];
                xp[b][0] = __double_as_longlong(xv.x);
                xp[b][1] = __double_as_longlong(xv.y);
            }
            #pragma unroll
            for (int h = 0; h < HHn; h++) {
                double2 wv = ((const double2*)w_s[h])[d4];
                u64 w0 = __double_as_longlong(wv.x);
                u64 w1v = __double_as_longlong(wv.y);
                #pragma unroll
                for (int b = 0; b < 4; b++) {
                    fma2(acc[b][h], xp[b][0], w0);
                    fma2(acc[b][h], xp[b][1], w1v);
                }
            }
        }
        float vals[32];
        #pragma unroll
        for (int b = 0; b < 4; b++)
            #pragma unroll
            for (int h = 0; h < HHn; h++) {
                float2 p = upk2(acc[b][h]);
                vals[b * 8 + h] = p.x + p.y;
            }
        #pragma unroll
        for (int s = 0; s < 5; s++) {
            const int n = 32 >> s;
            const int off = 1 << s;
            const bool up = (lane & off) != 0;
            #pragma unroll
            for (int i = 0; i < (n >> 1); i++) {
                float kept = up ? vals[i + (n >> 1)] : vals[i];
                float sent = up ? vals[i] : vals[i + (n >> 1)];
                float r = __shfl_xor_sync(0xffffffffu, sent, off);
                vals[i] = kept + r;
            }
        }
        logits[((size_t)(bs0 + jb) * HHn + jh) * LLn + l] = vals[0];
    }
}

// ---------------------------------------------------------------------------
// K2: fused softmax + ax. grid (bs=128, dhalf=2), block 256. fp16 split out.
// ---------------------------------------------------------------------------
__global__ __launch_bounds__(256) void ax_kernel(
    const float* __restrict__ x, const float* __restrict__ logits,
    const int* __restrict__ mask, float* __restrict__ attn_out,
    __half* __restrict__ axh, __half* __restrict__ axl)
{
    __shared__ float  a_s[HHn][LLn];
    __shared__ __align__(8) float2 ap[LLn][HHn/2];
    const int bs = blockIdx.x, dh = blockIdx.y;
    const int tid = threadIdx.x, warp = tid >> 5, lane = tid & 31;

    {
        const int h = warp;
        const int row = bs * HHn + h;
        const float invT = 0.0441941738241592f;
        float v[4], mx = -3.4e38f;
        #pragma unroll
        for (int i = 0; i < 4; i++) {
            int l = lane + 32 * i;
            float lg = logits[(size_t)row * LLn + l] * invT;
            if (mask[bs * LLn + l] == 0) lg = -1e9f;
            v[i] = lg; mx = fmaxf(mx, lg);
        }
        #pragma unroll
        for (int off = 16; off; off >>= 1)
            mx = fmaxf(mx, __shfl_xor_sync(0xffffffffu, mx, off));
        float sum = 0.f;
        #pragma unroll
        for (int i = 0; i < 4; i++) { v[i] = __expf(v[i] - mx); sum += v[i]; }
        #pragma unroll
        for (int off = 16; off; off >>= 1)
            sum += __shfl_xor_sync(0xffffffffu, sum, off);
        float inv = 1.f / sum;
        #pragma unroll
        for (int i = 0; i < 4; i++) {
            int l = lane + 32 * i;
            float a = v[i] * inv;
            a_s[h][l] = a;
            if (dh == 0 && attn_out) attn_out[(size_t)row * LLn + l] = a;
        }
    }
    __syncthreads();

    #pragma unroll
    for (int i = tid; i < LLn * 4; i += 256) {
        int l = i >> 2, p = i & 3;
        ap[l][p] = make_float2(a_s[2 * p][l], a_s[2 * p + 1][l]);
    }
    __syncthreads();

    const int d = dh * 256 + tid;
    const float* xp = x + (size_t)bs * LLn * DDn + d;

    u64 acc[4];
    #pragma unroll
    for (int p = 0; p < 4; p++) acc[p] = 0ull;

    #pragma unroll 8
    for (int l = 0; l < LLn; l++) {
        float xv = xp[(size_t)l * DDn];
        u64 xx = pk2(xv, xv);
        #pragma unroll
        for (int p = 0; p < 4; p++) {
            u64 av = __double_as_longlong(*(const double*)&ap[l][p]);
            fma2(acc[p], av, xx);
        }
    }
    #pragma unroll
    for (int p = 0; p < 4; p++) {
        float2 s = upk2(acc[p]);
        size_t o0 = ((size_t)bs * HHn + 2 * p) * DDn + d;
        size_t o1 = ((size_t)bs * HHn + 2 * p + 1) * DDn + d;
        __half hh, hl;
        hsplit(s.x, hh, hl); axh[o0] = hh; axl[o0] = hl;
        hsplit(s.y, hh, hl); axh[o1] = hh; axl[o1] = hl;
    }
}

// ---------------------------------------------------------------------------
// LayerNorm, 4 warps per row (1 float4/partial/thread), block 256 = 2 rows.
// grid NROW/2. Reduces NPART partials; optional single fp16 out.
// ---------------------------------------------------------------------------
template<int NPART, bool ADDBIAS, bool RES, bool SPLIT>
__global__ __launch_bounds__(256) void ln_kernel(
    const float* __restrict__ parts, const float* __restrict__ bias,
    const float* __restrict__ res,
    const float* __restrict__ g, const float* __restrict__ b,
    float* __restrict__ out, __half* __restrict__ oh)
{
    __shared__ float red[8][2];
    const int warp = threadIdx.x >> 5, lane = threadIdx.x & 31;
    const int wp = warp >> 2, qw = warp & 3;
    const int row = blockIdx.x * 2 + wp;
    const int off = qw * 128 + lane * 4;
    const size_t base = (size_t)row * DDn + off;

    float4 a0 = *(const float4*)(parts + base);
    float v[4] = { a0.x, a0.y, a0.z, a0.w };
    #pragma unroll
    for (int p = 1; p < NPART; p++) {
        float4 a = *(const float4*)(parts + (size_t)p * NROW * DDn + base);
        v[0] += a.x; v[1] += a.y; v[2] += a.z; v[3] += a.w;
    }
    if (ADDBIAS) {
        float4 a = *(const float4*)(bias + off);
        v[0] += a.x; v[1] += a.y; v[2] += a.z; v[3] += a.w;
    }
    if (RES) {
        float4 a = *(const float4*)(res + base);
        v[0] += a.x; v[1] += a.y; v[2] += a.z; v[3] += a.w;
    }

    float s = v[0] + v[1] + v[2] + v[3];
    float sq = v[0]*v[0] + v[1]*v[1] + v[2]*v[2] + v[3]*v[3];
    #pragma unroll
    for (int o2 = 16; o2; o2 >>= 1) {
        s  += __shfl_xor_sync(0xffffffffu, s,  o2);
        sq += __shfl_xor_sync(0xffffffffu, sq, o2);
    }
    if (lane == 0) { red[warp][0] = s; red[warp][1] = sq; }
    __syncthreads();
    float ts = red[wp*4+0][0] + red[wp*4+1][0] + red[wp*4+2][0] + red[wp*4+3][0];
    float tq = red[wp*4+0][1] + red[wp*4+1][1] + red[wp*4+2][1] + red[wp*4+3][1];
    float mu  = ts * (1.f / DDn);
    float var = tq * (1.f / DDn) - mu * mu;
    float inv = rsqrtf(var + 1e-6f);

    float4 gv = *(const float4*)(g + off);
    float4 bv = *(const float4*)(b + off);
    float y0 = (v[0] - mu) * inv * gv.x + bv.x;
    float y1 = (v[1] - mu) * inv * gv.y + bv.y;
    float y2 = (v[2] - mu) * inv * gv.z + bv.z;
    float y3 = (v[3] - mu) * inv * gv.w + bv.w;
    if (out)
        *(float4*)(out + base) = make_float4(y0, y1, y2, y3);
    if (SPLIT) {
        ushort4 hs = make_ushort4(
            __half_as_ushort(__float2half(y0)),
            __half_as_ushort(__float2half(y1)),
            __half_as_ushort(__float2half(y2)),
            __half_as_ushort(__float2half(y3)));
        *(uint2*)(oh + base) = *(uint2*)&hs;
    }
}

// ---------------------------------------------------------------------------
extern "C" void kernel_launch(void* const* d_in, const int* in_sizes, int n_in,
                              void* d_out, int out_size)
{
    const float* x    = (const float*)d_in[0];
    const int*   mask = (const int*)  d_in[1];
    const float* w    = (const float*)d_in[2];
    const float* v_w  = (const float*)d_in[3];
    const float* ln_g = (const float*)d_in[4];
    const float* ln_b = (const float*)d_in[5];
    const float* w1   = (const float*)d_in[6];
    const float* b1   = (const float*)d_in[7];
    const float* w2   = (const float*)d_in[8];
    const float* b2   = (const float*)d_in[9];
    const float* fg   = (const float*)d_in[10];
    const float* fb   = (const float*)d_in[11];

    float *o, *lg, *pp;
    __half *axh, *axl, *oh, *hh, *vwf, *w1f, *w2f;
    cudaGetSymbolAddress((void**)&o,   g_o);
    cudaGetSymbolAddress((void**)&lg,  g_logits);
    cudaGetSymbolAddress((void**)&pp,  g_p);
    cudaGetSymbolAddress((void**)&axh, g_axh);
    cudaGetSymbolAddress((void**)&axl, g_axl);
    cudaGetSymbolAddress((void**)&oh,  g_oh);
    cudaGetSymbolAddress((void**)&hh,  g_hh);
    cudaGetSymbolAddress((void**)&vwf, g_vwf);
    cudaGetSymbolAddress((void**)&w1f, g_w1f);
    cudaGetSymbolAddress((void**)&w2f, g_w2f);

    float* y_out = (float*)d_out;
    float* attn_out = (out_size >= NROW * DDn + NROW * LLn)
                        ? (y_out + NROW * DDn) : nullptr;

    constexpr int SMG2 = 4 * (2 * 128 * 64 + 128 * 64);   // 98304 (ASPLIT=1)
    constexpr int SMG1 = 4 * (128 * 64 + 128 * 64);       // 65536 (ASPLIT=0)
    cudaFuncSetAttribute(gemm_mma<1, 0>,
                         cudaFuncAttributeMaxDynamicSharedMemorySize, SMG2);
    cudaFuncSetAttribute(gemm_mma<0, 1>,
                         cudaFuncAttributeMaxDynamicSharedMemorySize, SMG1);
    cudaFuncSetAttribute(gemm_mma<0, 0>,
                         cudaFuncAttributeMaxDynamicSharedMemorySize, SMG1);

    // K1 union: logits (256 blocks) + weight fp32->fp16 conversion (2304)
    constexpr int NCONV = (DDn*DDn + DIn*DDn + DDn*DIn) / 4 / 256;  // 2304
    logits_conv_kernel<<<256 + NCONV, 256>>>(
        x, w, lg, (const float4*)v_w, (const float4*)w1, (const float4*)w2,
        vwf, w1f, w2f);

    // K2: fused softmax + attn@x (fp16 split out)
    ax_kernel<<<dim3(NBS, 2), 256>>>(x, lg, mask, attn_out, axh, axl);

    // G0: (axh+axl) @ vwf^T, split-K4 -> p0..p3  (1024 x 512 x 512, KT=4)
    gemm_mma<1, 0><<<dim3(DDn/128, NROW/128, 4), 256, SMG2>>>(
        axh, axl, vwf, nullptr, pp, nullptr,
        NROW, DDn, DDn);

    // o = LN(p0..p3) (+ single fp16 out)
    ln_kernel<4, false, false, true><<<NROW/2, 256>>>(
        pp, nullptr, nullptr, ln_g, ln_b, o, oh);

    // G1: hh = fp16(relu(oh @ w1f^T + b1)), single MMA (1024 x 2048 x 512)
    gemm_mma<0, 1><<<dim3(DIn/128, NROW/128, 1), 256, SMG1>>>(
        oh, nullptr, w1f, b1, nullptr, hh,
        NROW, DIn, DDn);

    // G2: hh @ w2f^T, single MMA, split-K4 -> p0..p3 (1024 x 512 x 2048)
    gemm_mma<0, 0><<<dim3(DDn/128, NROW/128, 4), 256, SMG1>>>(
        hh, nullptr, w2f, nullptr, pp, nullptr,
        NROW, DDn, DIn);

    // y = LN(sum p + b2 + o)
    ln_kernel<4, true, true, false><<<NROW/2, 256>>>(
        pp, b2, o, fg, fb, y_out, nullptr);
}

// round 16
// speedup vs baseline: 1.4838x; 1.0039x over previous
#include <cuda_runtime.h>
#include <cuda_fp16.h>
#include <cstdint>

#define HHn 8
#define LLn 128
#define DDn 512
#define DIn 2048
#define NBS 128
#define NROW 1024

typedef unsigned long long u64;

// ---------------- scratch (device globals; no allocation allowed) ----------
__device__ float g_o  [NROW*DDn];
__device__ float g_logits[NROW*LLn];
__device__ float g_p  [4][NROW*DDn];    // split-K partials
__device__ __half g_axh[NROW*DDn];
__device__ __half g_oh [NROW*DDn];
__device__ __half g_hh [NROW*DIn];
__device__ __half g_vwf[DDn*DDn];
__device__ __half g_w1f[DIn*DDn];
__device__ __half g_w2f[DDn*DIn];

// ---------------- helpers ---------------------------------------------------
__device__ __forceinline__ uint32_t smem_u32(const void* p) {
    uint32_t a;
    asm("{ .reg .u64 t; cvta.to.shared.u64 t, %1; cvt.u32.u64 %0, t; }"
        : "=r"(a) : "l"(p));
    return a;
}
__device__ __forceinline__ void fma2(u64 &d, u64 a, u64 b) {
    asm("fma.rn.f32x2 %0, %1, %2, %0;" : "+l"(d) : "l"(a), "l"(b));
}
__device__ __forceinline__ u64 pk2(float a, float b) {
    u64 r; asm("mov.b64 %0, {%1,%2};" : "=l"(r) : "f"(a), "f"(b)); return r;
}
__device__ __forceinline__ float2 upk2(u64 v) {
    float2 r; asm("mov.b64 {%0,%1}, %2;" : "=f"(r.x), "=f"(r.y) : "l"(v)); return r;
}

#define CPA16(dst, src) \
    asm volatile("cp.async.cg.shared.global [%0], [%1], 16;" \
                 :: "r"(dst), "l"(src) : "memory")
#define CPA_COMMIT() asm volatile("cp.async.commit_group;" ::: "memory")
#define CPA_WAIT(n)  asm volatile("cp.async.wait_group %0;" :: "n"(n) : "memory")

#define LDSM4(r, addr) \
    asm volatile("ldmatrix.sync.aligned.m8n8.x4.shared.b16 {%0,%1,%2,%3}, [%4];" \
                 : "=r"((r)[0]), "=r"((r)[1]), "=r"((r)[2]), "=r"((r)[3]) \
                 : "r"(addr))

#define MMA_F16(c, a, b) \
    asm volatile("mma.sync.aligned.m16n8k16.row.col.f32.f16.f16.f32 " \
        "{%0,%1,%2,%3}, {%4,%5,%6,%7}, {%8,%9}, {%0,%1,%2,%3};" \
        : "+f"((c)[0]), "+f"((c)[1]), "+f"((c)[2]), "+f"((c)[3]) \
        : "r"((a)[0]), "r"((a)[1]), "r"((a)[2]), "r"((a)[3]), \
          "r"((b)[0]), "r"((b)[1]))

// 64-byte smem rows (BK=32 fp16), 4 chunks of 16B, 2-bit XOR swizzle.
__device__ __forceinline__ uint32_t tile_off(int row, int chunk) {
    return (uint32_t)(row * 64 + ((chunk ^ ((row >> 1) & 3)) << 4));
}

// ---------------------------------------------------------------------------
// HMMA fp16 GEMM. ASPLIT=1: A = Ah+Al (2 MMAs); ASPLIT=0: A = Ah (1 MMA).
// BM=BN=128, BK=32, 4-stage pipeline, 256 threads, warp tile 64x32.
// EPI=0: fp32 partial store to C + z*M*N (split-K over blockIdx.z).
// EPI=1: bias + relu + single fp16 store to Ch.
// ---------------------------------------------------------------------------
template<int ASPLIT, int EPI>
__global__ __launch_bounds__(256, 2) void gemm_mma(
    const __half* __restrict__ Ah, const __half* __restrict__ Al,
    const __half* __restrict__ Bf,
    const float* __restrict__ bias, float* __restrict__ C,
    __half* __restrict__ Ch,
    int M, int N, int K)
{
    constexpr int BM = 128, BN = 128, BK = 32, STAGES = 4, THREADS = 256;
    constexpr int WM = 2, WN = 4;
    constexpr int NA = 1 + ASPLIT;
    constexpr int A_BYTES = BM * 64;
    constexpr int B_BYTES = BN * 64;
    constexpr int STAGE = NA * A_BYTES + B_BYTES;
    constexpr int MT = (BM / WM) / 16;             // 4
    constexpr int NT = (BN / WN) / 8;              // 4
    constexpr int CHUNKS = (NA * BM + BN) * 4;
    constexpr int CPT = CHUNKS / THREADS;

    extern __shared__ __align__(128) char dsm[];
    const uint32_t sb = smem_u32(dsm);

    const int tid = threadIdx.x, wid = tid >> 5, lane = tid & 31;
    const int bm = blockIdx.y * BM, bn = blockIdx.x * BN;
    const int wm = wid / WN, wn = wid % WN;
    const int KT = (K / BK) / gridDim.z;
    const int kt0 = blockIdx.z * KT;

    auto load_stage = [&](int kt, int s) {
        const uint32_t base = sb + s * STAGE;
        const size_t gk = (size_t)(kt0 + kt) * BK;
        #pragma unroll
        for (int i = 0; i < CPT; i++) {
            int id = tid + i * THREADS;
            int row_all = id >> 2;
            int ck = id & 3;
            const __half* g;
            uint32_t abase; int row; int rowbase;
            if (row_all < BM) {
                g = Ah; abase = 0; row = row_all; rowbase = bm;
            } else if (ASPLIT && row_all < 2 * BM) {
                g = Al; abase = A_BYTES; row = row_all - BM; rowbase = bm;
            } else {
                g = Bf; abase = NA * A_BYTES; row = row_all - NA * BM; rowbase = bn;
            }
            const __half* src =
                g + (size_t)(rowbase + row) * K + gk + ck * 8;
            CPA16(base + abase + tile_off(row, ck), src);
        }
        CPA_COMMIT();
    };

    float c[MT][NT][4];
    #pragma unroll
    for (int i = 0; i < MT; i++)
        #pragma unroll
        for (int j = 0; j < NT; j++)
            #pragma unroll
            for (int q = 0; q < 4; q++) c[i][j][q] = 0.f;

    load_stage(0, 0);
    if (1 < KT) load_stage(1, 1);
    if (2 < KT) load_stage(2, 2);
    CPA_WAIT(2);
    __syncthreads();

    const int aRow0 = wm * (BM / WM);
    const int bRow0 = wn * (BN / WN);

    for (int kt = 0; kt < KT; kt++) {
        const uint32_t base = sb + (kt % STAGES) * STAGE;
        const uint32_t sAh = base;
        const uint32_t sAl = base + A_BYTES;
        const uint32_t sB  = base + NA * A_BYTES;

        #pragma unroll
        for (int ks = 0; ks < 2; ks++) {
            uint32_t aH[MT][4], aL[MT][4];
            #pragma unroll
            for (int mt = 0; mt < MT; mt++) {
                int row = aRow0 + mt * 16 + (lane & 15);
                int ck = ks * 2 + (lane >> 4);
                uint32_t off = tile_off(row, ck);
                LDSM4(aH[mt], sAh + off);
                if (ASPLIT) LDSM4(aL[mt], sAl + off);
            }
            uint32_t bR[NT][2];
            #pragma unroll
            for (int p = 0; p < NT / 2; p++) {
                int row = bRow0 + p * 16 + (lane & 7) + ((lane >> 4) << 3);
                int ck = ks * 2 + ((lane >> 3) & 1);
                uint32_t r[4];
                LDSM4(r, sB + tile_off(row, ck));
                bR[2*p][0] = r[0]; bR[2*p][1] = r[1];
                bR[2*p+1][0] = r[2]; bR[2*p+1][1] = r[3];
            }
            #pragma unroll
            for (int mt = 0; mt < MT; mt++)
                #pragma unroll
                for (int nt = 0; nt < NT; nt++) {
                    MMA_F16(c[mt][nt], aH[mt], bR[nt]);
                    if (ASPLIT) MMA_F16(c[mt][nt], aL[mt], bR[nt]);
                }
        }

        if (kt + 3 < KT) {
            load_stage(kt + 3, (kt + 3) % STAGES);
            CPA_WAIT(2);
        } else {
            CPA_WAIT(0);
        }
        __syncthreads();
    }

    // ---- epilogue ----
    float* Cz = C + (size_t)blockIdx.z * M * N;
    #pragma unroll
    for (int mt = 0; mt < MT; mt++) {
        #pragma unroll
        for (int nt = 0; nt < NT; nt++) {
            int row = bm + aRow0 + mt * 16 + (lane >> 2);
            int col = bn + bRow0 + nt * 8 + ((lane & 3) << 1);
            #pragma unroll
            for (int half = 0; half < 2; half++) {
                int r = row + half * 8;
                float v0 = c[mt][nt][half * 2 + 0];
                float v1 = c[mt][nt][half * 2 + 1];
                if (EPI == 0) {
                    Cz[(size_t)r * N + col]     = v0;
                    Cz[(size_t)r * N + col + 1] = v1;
                } else {
                    v0 = fmaxf(v0 + bias[col], 0.f);
                    v1 = fmaxf(v1 + bias[col + 1], 0.f);
                    Ch[(size_t)r * N + col]     = __float2half(v0);
                    Ch[(size_t)r * N + col + 1] = __float2half(v1);
                }
            }
        }
    }
}

// ---------------------------------------------------------------------------
// K1 union: blocks [0,256) compute logits; blocks [256, 256+2304) convert the
// three weight tensors fp32 -> fp16 (overlapped in one launch).
// ---------------------------------------------------------------------------
__global__ __launch_bounds__(256) void logits_conv_kernel(
    const float* __restrict__ x, const float* __restrict__ w,
    float* __restrict__ logits,
    const float4* __restrict__ vw, const float4* __restrict__ w1,
    const float4* __restrict__ w2,
    __half* __restrict__ vwf, __half* __restrict__ w1f, __half* __restrict__ w2f)
{
    if (blockIdx.x >= 256) {
        constexpr int N0 = DDn * DDn / 4;
        constexpr int N1 = DIn * DDn / 4;
        int i = (blockIdx.x - 256) * 256 + threadIdx.x;
        const float4* in; __half* dst; int k;
        if (i < N0)            { in = vw; dst = vwf; k = i; }
        else if (i < N0 + N1)  { in = w1; dst = w1f; k = i - N0; }
        else                   { in = w2; dst = w2f; k = i - N0 - N1; }
        float4 v = in[k];
        ushort4 o4 = make_ushort4(
            __half_as_ushort(__float2half(v.x)),
            __half_as_ushort(__float2half(v.y)),
            __half_as_ushort(__float2half(v.z)),
            __half_as_ushort(__float2half(v.w)));
        *(ushort4*)(dst + 4 * (size_t)k) = o4;
        return;
    }

    __shared__ __align__(16) float w_s[HHn][DDn];
    const int l = blockIdx.x & 127, half = blockIdx.x >> 7;
    const int tid = threadIdx.x, warp = tid >> 5, lane = tid & 31;

    #pragma unroll
    for (int i = 0; i < 4; i++) {
        int idx = tid + i * 256;
        int h = idx >> 7, d4 = idx & 127;
        ((float4*)w_s[h])[d4] =
            ((const float4*)(w + ((size_t)(h * LLn + l)) * DDn))[d4];
    }
    __syncthreads();

    const int j  = __brev((unsigned)lane) >> 27;
    const int jb = j >> 3, jh = j & 7;

    #pragma unroll
    for (int q = 0; q < 2; q++) {
        const int bs0 = half * 64 + warp * 8 + q * 4;
        u64 acc[4][HHn];
        #pragma unroll
        for (int b = 0; b < 4; b++)
            #pragma unroll
            for (int h = 0; h < HHn; h++) acc[b][h] = 0ull;

        #pragma unroll
        for (int c = 0; c < 4; c++) {
            const int d4 = c * 32 + lane;
            u64 xp[4][2];
            #pragma unroll
            for (int b = 0; b < 4; b++) {
                double2 xv = ((const double2*)
                    (x + ((size_t)((bs0 + b) * LLn + l)) * DDn))[d4];
                xp[b][0] = __double_as_longlong(xv.x);
                xp[b][1] = __double_as_longlong(xv.y);
            }
            #pragma unroll
            for (int h = 0; h < HHn; h++) {
                double2 wv = ((const double2*)w_s[h])[d4];
                u64 w0 = __double_as_longlong(wv.x);
                u64 w1v = __double_as_longlong(wv.y);
                #pragma unroll
                for (int b = 0; b < 4; b++) {
                    fma2(acc[b][h], xp[b][0], w0);
                    fma2(acc[b][h], xp[b][1], w1v);
                }
            }
        }
        float vals[32];
        #pragma unroll
        for (int b = 0; b < 4; b++)
            #pragma unroll
            for (int h = 0; h < HHn; h++) {
                float2 p = upk2(acc[b][h]);
                vals[b * 8 + h] = p.x + p.y;
            }
        #pragma unroll
        for (int s = 0; s < 5; s++) {
            const int n = 32 >> s;
            const int off = 1 << s;
            const bool up = (lane & off) != 0;
            #pragma unroll
            for (int i = 0; i < (n >> 1); i++) {
                float kept = up ? vals[i + (n >> 1)] : vals[i];
                float sent = up ? vals[i] : vals[i + (n >> 1)];
                float r = __shfl_xor_sync(0xffffffffu, sent, off);
                vals[i] = kept + r;
            }
        }
        logits[((size_t)(bs0 + jb) * HHn + jh) * LLn + l] = vals[0];
    }
}

// ---------------------------------------------------------------------------
// K2: fused softmax + ax. grid (bs=128, dhalf=2), block 256. fp16 out.
// ---------------------------------------------------------------------------
__global__ __launch_bounds__(256) void ax_kernel(
    const float* __restrict__ x, const float* __restrict__ logits,
    const int* __restrict__ mask, float* __restrict__ attn_out,
    __half* __restrict__ axh)
{
    __shared__ float  a_s[HHn][LLn];
    __shared__ __align__(8) float2 ap[LLn][HHn/2];
    const int bs = blockIdx.x, dh = blockIdx.y;
    const int tid = threadIdx.x, warp = tid >> 5, lane = tid & 31;

    {
        const int h = warp;
        const int row = bs * HHn + h;
        const float invT = 0.0441941738241592f;
        float v[4], mx = -3.4e38f;
        #pragma unroll
        for (int i = 0; i < 4; i++) {
            int l = lane + 32 * i;
            float lg = logits[(size_t)row * LLn + l] * invT;
            if (mask[bs * LLn + l] == 0) lg = -1e9f;
            v[i] = lg; mx = fmaxf(mx, lg);
        }
        #pragma unroll
        for (int off = 16; off; off >>= 1)
            mx = fmaxf(mx, __shfl_xor_sync(0xffffffffu, mx, off));
        float sum = 0.f;
        #pragma unroll
        for (int i = 0; i < 4; i++) { v[i] = __expf(v[i] - mx); sum += v[i]; }
        #pragma unroll
        for (int off = 16; off; off >>= 1)
            sum += __shfl_xor_sync(0xffffffffu, sum, off);
        float inv = 1.f / sum;
        #pragma unroll
        for (int i = 0; i < 4; i++) {
            int l = lane + 32 * i;
            float a = v[i] * inv;
            a_s[h][l] = a;
            if (dh == 0 && attn_out) attn_out[(size_t)row * LLn + l] = a;
        }
    }
    __syncthreads();

    #pragma unroll
    for (int i = tid; i < LLn * 4; i += 256) {
        int l = i >> 2, p = i & 3;
        ap[l][p] = make_float2(a_s[2 * p][l], a_s[2 * p + 1][l]);
    }
    __syncthreads();

    const int d = dh * 256 + tid;
    const float* xp = x + (size_t)bs * LLn * DDn + d;

    u64 acc[4];
    #pragma unroll
    for (int p = 0; p < 4; p++) acc[p] = 0ull;

    #pragma unroll 8
    for (int l = 0; l < LLn; l++) {
        float xv = xp[(size_t)l * DDn];
        u64 xx = pk2(xv, xv);
        #pragma unroll
        for (int p = 0; p < 4; p++) {
            u64 av = __double_as_longlong(*(const double*)&ap[l][p]);
            fma2(acc[p], av, xx);
        }
    }
    #pragma unroll
    for (int p = 0; p < 4; p++) {
        float2 s = upk2(acc[p]);
        size_t o0 = ((size_t)bs * HHn + 2 * p) * DDn + d;
        size_t o1 = ((size_t)bs * HHn + 2 * p + 1) * DDn + d;
        axh[o0] = __float2half(s.x);
        axh[o1] = __float2half(s.y);
    }
}

// ---------------------------------------------------------------------------
// LayerNorm, 8 warps per row (float2/thread), block 256 = 1 row, grid NROW.
// Reduces NPART partials; optional single fp16 out.
// ---------------------------------------------------------------------------
template<int NPART, bool ADDBIAS, bool RES, bool SPLIT>
__global__ __launch_bounds__(256) void ln_kernel(
    const float* __restrict__ parts, const float* __restrict__ bias,
    const float* __restrict__ res,
    const float* __restrict__ g, const float* __restrict__ b,
    float* __restrict__ out, __half* __restrict__ oh)
{
    __shared__ float red[8][2];
    const int warp = threadIdx.x >> 5, lane = threadIdx.x & 31;
    const int row = blockIdx.x;
    const int off = warp * 64 + lane * 2;
    const size_t base = (size_t)row * DDn + off;

    float2 a0 = *(const float2*)(parts + base);
    float v0 = a0.x, v1 = a0.y;
    #pragma unroll
    for (int p = 1; p < NPART; p++) {
        float2 a = *(const float2*)(parts + (size_t)p * NROW * DDn + base);
        v0 += a.x; v1 += a.y;
    }
    if (ADDBIAS) {
        float2 a = *(const float2*)(bias + off);
        v0 += a.x; v1 += a.y;
    }
    if (RES) {
        float2 a = *(const float2*)(res + base);
        v0 += a.x; v1 += a.y;
    }

    float s = v0 + v1;
    float sq = v0 * v0 + v1 * v1;
    #pragma unroll
    for (int o2 = 16; o2; o2 >>= 1) {
        s  += __shfl_xor_sync(0xffffffffu, s,  o2);
        sq += __shfl_xor_sync(0xffffffffu, sq, o2);
    }
    if (lane == 0) { red[warp][0] = s; red[warp][1] = sq; }
    __syncthreads();
    float ts = 0.f, tq = 0.f;
    #pragma unroll
    for (int k = 0; k < 8; k++) { ts += red[k][0]; tq += red[k][1]; }
    float mu  = ts * (1.f / DDn);
    float var = tq * (1.f / DDn) - mu * mu;
    float inv = rsqrtf(var + 1e-6f);

    float2 gv = *(const float2*)(g + off);
    float2 bv = *(const float2*)(b + off);
    float y0 = (v0 - mu) * inv * gv.x + bv.x;
    float y1 = (v1 - mu) * inv * gv.y + bv.y;
    if (out)
        *(float2*)(out + base) = make_float2(y0, y1);
    if (SPLIT) {
        ushort2 hs = make_ushort2(
            __half_as_ushort(__float2half(y0)),
            __half_as_ushort(__float2half(y1)));
        *(uint32_t*)(oh + base) = *(uint32_t*)&hs;
    }
}

// ---------------------------------------------------------------------------
extern "C" void kernel_launch(void* const* d_in, const int* in_sizes, int n_in,
                              void* d_out, int out_size)
{
    const float* x    = (const float*)d_in[0];
    const int*   mask = (const int*)  d_in[1];
    const float* w    = (const float*)d_in[2];
    const float* v_w  = (const float*)d_in[3];
    const float* ln_g = (const float*)d_in[4];
    const float* ln_b = (const float*)d_in[5];
    const float* w1   = (const float*)d_in[6];
    const float* b1   = (const float*)d_in[7];
    const float* w2   = (const float*)d_in[8];
    const float* b2   = (const float*)d_in[9];
    const float* fg   = (const float*)d_in[10];
    const float* fb   = (const float*)d_in[11];

    float *o, *lg, *pp;
    __half *axh, *oh, *hh, *vwf, *w1f, *w2f;
    cudaGetSymbolAddress((void**)&o,   g_o);
    cudaGetSymbolAddress((void**)&lg,  g_logits);
    cudaGetSymbolAddress((void**)&pp,  g_p);
    cudaGetSymbolAddress((void**)&axh, g_axh);
    cudaGetSymbolAddress((void**)&oh,  g_oh);
    cudaGetSymbolAddress((void**)&hh,  g_hh);
    cudaGetSymbolAddress((void**)&vwf, g_vwf);
    cudaGetSymbolAddress((void**)&w1f, g_w1f);
    cudaGetSymbolAddress((void**)&w2f, g_w2f);

    float* y_out = (float*)d_out;
    float* attn_out = (out_size >= NROW * DDn + NROW * LLn)
                        ? (y_out + NROW * DDn) : nullptr;

    constexpr int SMG1 = 4 * (128 * 64 + 128 * 64);   // 65536 (ASPLIT=0)
    cudaFuncSetAttribute(gemm_mma<0, 0>,
                         cudaFuncAttributeMaxDynamicSharedMemorySize, SMG1);
    cudaFuncSetAttribute(gemm_mma<0, 1>,
                         cudaFuncAttributeMaxDynamicSharedMemorySize, SMG1);

    // K1 union: logits (256 blocks) + weight fp32->fp16 conversion (2304)
    constexpr int NCONV = (DDn*DDn + DIn*DDn + DDn*DIn) / 4 / 256;  // 2304
    logits_conv_kernel<<<256 + NCONV, 256>>>(
        x, w, lg, (const float4*)v_w, (const float4*)w1, (const float4*)w2,
        vwf, w1f, w2f);

    // K2: fused softmax + attn@x (fp16 out)
    ax_kernel<<<dim3(NBS, 2), 256>>>(x, lg, mask, attn_out, axh);

    // G0: axh @ vwf^T, single MMA, split-K4 -> p0..p3  (1024 x 512 x 512)
    gemm_mma<0, 0><<<dim3(DDn/128, NROW/128, 4), 256, SMG1>>>(
        axh, nullptr, vwf, nullptr, pp, nullptr,
        NROW, DDn, DDn);

    // o = LN(p0..p3) (+ single fp16 out)
    ln_kernel<4, false, false, true><<<NROW, 256>>>(
        pp, nullptr, nullptr, ln_g, ln_b, o, oh);

    // G1: hh = fp16(relu(oh @ w1f^T + b1)), single MMA (1024 x 2048 x 512)
    gemm_mma<0, 1><<<dim3(DIn/128, NROW/128, 1), 256, SMG1>>>(
        oh, nullptr, w1f, b1, nullptr, hh,
        NROW, DIn, DDn);

    // G2: hh @ w2f^T, single MMA, split-K4 -> p0..p3 (1024 x 512 x 2048)
    gemm_mma<0, 0><<<dim3(DDn/128, NROW/128, 4), 256, SMG1>>>(
        hh, nullptr, w2f, nullptr, pp, nullptr,
        NROW, DDn, DIn);

    // y = LN(sum p + b2 + o)
    ln_kernel<4, true, true, false><<<NROW, 256>>>(
        pp, b2, o, fg, fb, y_out, nullptr);
}

// round 17
// speedup vs baseline: 1.8860x; 1.2711x over previous
#include <cuda_runtime.h>
#include <cuda_fp16.h>
#include <cstdint>

#define HHn 8
#define LLn 128
#define DDn 512
#define DIn 2048
#define NBS 128
#define NROW 1024

typedef unsigned long long u64;

// ---------------- scratch (device globals; no allocation allowed) ----------
__device__ float g_o  [NROW*DDn];
__device__ float g_logits[NROW*LLn];
__device__ __half g_p  [4][NROW*DDn];   // fp16 split-K partials
__device__ __half g_axh[NROW*DDn];
__device__ __half g_oh [NROW*DDn];
__device__ __half g_hh [NROW*DIn];
__device__ __half g_vwf[DDn*DDn];
__device__ __half g_w1f[DIn*DDn];
__device__ __half g_w2f[DDn*DIn];

// ---------------- helpers ---------------------------------------------------
__device__ __forceinline__ uint32_t smem_u32(const void* p) {
    uint32_t a;
    asm("{ .reg .u64 t; cvta.to.shared.u64 t, %1; cvt.u32.u64 %0, t; }"
        : "=r"(a) : "l"(p));
    return a;
}
__device__ __forceinline__ void fma2(u64 &d, u64 a, u64 b) {
    asm("fma.rn.f32x2 %0, %1, %2, %0;" : "+l"(d) : "l"(a), "l"(b));
}
__device__ __forceinline__ u64 pk2(float a, float b) {
    u64 r; asm("mov.b64 %0, {%1,%2};" : "=l"(r) : "f"(a), "f"(b)); return r;
}
__device__ __forceinline__ float2 upk2(u64 v) {
    float2 r; asm("mov.b64 {%0,%1}, %2;" : "=f"(r.x), "=f"(r.y) : "l"(v)); return r;
}

#define CPA16(dst, src) \
    asm volatile("cp.async.cg.shared.global [%0], [%1], 16;" \
                 :: "r"(dst), "l"(src) : "memory")
#define CPA_COMMIT() asm volatile("cp.async.commit_group;" ::: "memory")
#define CPA_WAIT(n)  asm volatile("cp.async.wait_group %0;" :: "n"(n) : "memory")

#define LDSM4(r, addr) \
    asm volatile("ldmatrix.sync.aligned.m8n8.x4.shared.b16 {%0,%1,%2,%3}, [%4];" \
                 : "=r"((r)[0]), "=r"((r)[1]), "=r"((r)[2]), "=r"((r)[3]) \
                 : "r"(addr))

#define MMA_F16(c, a, b) \
    asm volatile("mma.sync.aligned.m16n8k16.row.col.f32.f16.f16.f32 " \
        "{%0,%1,%2,%3}, {%4,%5,%6,%7}, {%8,%9}, {%0,%1,%2,%3};" \
        : "+f"((c)[0]), "+f"((c)[1]), "+f"((c)[2]), "+f"((c)[3]) \
        : "r"((a)[0]), "r"((a)[1]), "r"((a)[2]), "r"((a)[3]), \
          "r"((b)[0]), "r"((b)[1]))

// 64-byte smem rows (BK=32 fp16), 4 chunks of 16B, 2-bit XOR swizzle.
__device__ __forceinline__ uint32_t tile_off(int row, int chunk) {
    return (uint32_t)(row * 64 + ((chunk ^ ((row >> 1) & 3)) << 4));
}

// ---------------------------------------------------------------------------
// HMMA fp16 GEMM (single-MMA). BM=BN=128, BK=32, 4-stage pipeline, 256 thr.
// EPI=0: fp16 partial store to Ph + z*M*N (split-K over blockIdx.z).
// EPI=1: bias + relu + fp16 store to Ph.
// ---------------------------------------------------------------------------
template<int EPI>
__global__ __launch_bounds__(256, 2) void gemm_mma(
    const __half* __restrict__ Ah, const __half* __restrict__ Bf,
    const float* __restrict__ bias, __half* __restrict__ Ph,
    int M, int N, int K)
{
    constexpr int BM = 128, BN = 128, BK = 32, STAGES = 4, THREADS = 256;
    constexpr int WM = 2, WN = 4;
    constexpr int A_BYTES = BM * 64;
    constexpr int B_BYTES = BN * 64;
    constexpr int STAGE = A_BYTES + B_BYTES;
    constexpr int MT = (BM / WM) / 16;             // 4
    constexpr int NT = (BN / WN) / 8;              // 4
    constexpr int CHUNKS = (BM + BN) * 4;          // 1024
    constexpr int CPT = CHUNKS / THREADS;          // 4

    extern __shared__ __align__(128) char dsm[];
    const uint32_t sb = smem_u32(dsm);

    const int tid = threadIdx.x, wid = tid >> 5, lane = tid & 31;
    const int bm = blockIdx.y * BM, bn = blockIdx.x * BN;
    const int wm = wid / WN, wn = wid % WN;
    const int KT = (K / BK) / gridDim.z;
    const int kt0 = blockIdx.z * KT;

    auto load_stage = [&](int kt, int s) {
        const uint32_t base = sb + s * STAGE;
        const size_t gk = (size_t)(kt0 + kt) * BK;
        #pragma unroll
        for (int i = 0; i < CPT; i++) {
            int id = tid + i * THREADS;
            int row_all = id >> 2;
            int ck = id & 3;
            const __half* g;
            uint32_t abase; int row; int rowbase;
            if (row_all < BM) {
                g = Ah; abase = 0; row = row_all; rowbase = bm;
            } else {
                g = Bf; abase = A_BYTES; row = row_all - BM; rowbase = bn;
            }
            const __half* src =
                g + (size_t)(rowbase + row) * K + gk + ck * 8;
            CPA16(base + abase + tile_off(row, ck), src);
        }
        CPA_COMMIT();
    };

    float c[MT][NT][4];
    #pragma unroll
    for (int i = 0; i < MT; i++)
        #pragma unroll
        for (int j = 0; j < NT; j++)
            #pragma unroll
            for (int q = 0; q < 4; q++) c[i][j][q] = 0.f;

    load_stage(0, 0);
    if (1 < KT) load_stage(1, 1);
    if (2 < KT) load_stage(2, 2);
    CPA_WAIT(2);
    __syncthreads();

    const int aRow0 = wm * (BM / WM);
    const int bRow0 = wn * (BN / WN);

    for (int kt = 0; kt < KT; kt++) {
        const uint32_t base = sb + (kt % STAGES) * STAGE;
        const uint32_t sA = base;
        const uint32_t sB = base + A_BYTES;

        #pragma unroll
        for (int ks = 0; ks < 2; ks++) {
            uint32_t aR[MT][4];
            #pragma unroll
            for (int mt = 0; mt < MT; mt++) {
                int row = aRow0 + mt * 16 + (lane & 15);
                int ck = ks * 2 + (lane >> 4);
                LDSM4(aR[mt], sA + tile_off(row, ck));
            }
            uint32_t bR[NT][2];
            #pragma unroll
            for (int p = 0; p < NT / 2; p++) {
                int row = bRow0 + p * 16 + (lane & 7) + ((lane >> 4) << 3);
                int ck = ks * 2 + ((lane >> 3) & 1);
                uint32_t r[4];
                LDSM4(r, sB + tile_off(row, ck));
                bR[2*p][0] = r[0]; bR[2*p][1] = r[1];
                bR[2*p+1][0] = r[2]; bR[2*p+1][1] = r[3];
            }
            #pragma unroll
            for (int mt = 0; mt < MT; mt++)
                #pragma unroll
                for (int nt = 0; nt < NT; nt++)
                    MMA_F16(c[mt][nt], aR[mt], bR[nt]);
        }

        if (kt + 3 < KT) {
            load_stage(kt + 3, (kt + 3) % STAGES);
            CPA_WAIT(2);
        } else {
            CPA_WAIT(0);
        }
        __syncthreads();
    }

    // ---- epilogue: fp16 stores ----
    __half* Pz = Ph + (size_t)blockIdx.z * M * N;
    #pragma unroll
    for (int mt = 0; mt < MT; mt++) {
        #pragma unroll
        for (int nt = 0; nt < NT; nt++) {
            int row = bm + aRow0 + mt * 16 + (lane >> 2);
            int col = bn + bRow0 + nt * 8 + ((lane & 3) << 1);
            #pragma unroll
            for (int half = 0; half < 2; half++) {
                int r = row + half * 8;
                float v0 = c[mt][nt][half * 2 + 0];
                float v1 = c[mt][nt][half * 2 + 1];
                if (EPI == 1) {
                    v0 = fmaxf(v0 + bias[col], 0.f);
                    v1 = fmaxf(v1 + bias[col + 1], 0.f);
                }
                __half2 hv = __floats2half2_rn(v0, v1);
                *(__half2*)(Pz + (size_t)r * N + col) = hv;
            }
        }
    }
}

// ---------------------------------------------------------------------------
// K1 union: blocks [0,512) compute logits (l = bx&127, quarter = bx>>7);
// blocks [512, 512+576) convert weights fp32->fp16 at MLP 4.
// ---------------------------------------------------------------------------
__global__ __launch_bounds__(256) void logits_conv_kernel(
    const float* __restrict__ x, const float* __restrict__ w,
    float* __restrict__ logits,
    const float4* __restrict__ vw, const float4* __restrict__ w1,
    const float4* __restrict__ w2,
    __half* __restrict__ vwf, __half* __restrict__ w1f, __half* __restrict__ w2f)
{
    if (blockIdx.x >= 512) {
        constexpr int N0 = DDn * DDn / 4;
        constexpr int N1 = DIn * DDn / 4;
        int ib = (blockIdx.x - 512) * 1024 + threadIdx.x;
        #pragma unroll
        for (int k = 0; k < 4; k++) {
            int i = ib + k * 256;
            const float4* in; __half* dst; int idx;
            if (i < N0)            { in = vw; dst = vwf; idx = i; }
            else if (i < N0 + N1)  { in = w1; dst = w1f; idx = i - N0; }
            else                   { in = w2; dst = w2f; idx = i - N0 - N1; }
            float4 v = in[idx];
            __half2 h0 = __floats2half2_rn(v.x, v.y);
            __half2 h1 = __floats2half2_rn(v.z, v.w);
            uint2 o2;
            o2.x = *(uint32_t*)&h0; o2.y = *(uint32_t*)&h1;
            *(uint2*)(dst + 4 * (size_t)idx) = o2;
        }
        return;
    }

    __shared__ __align__(16) float w_s[HHn][DDn];
    const int l = blockIdx.x & 127, quarter = blockIdx.x >> 7;
    const int tid = threadIdx.x, warp = tid >> 5, lane = tid & 31;

    #pragma unroll
    for (int i = 0; i < 4; i++) {
        int idx = tid + i * 256;
        int h = idx >> 7, d4 = idx & 127;
        ((float4*)w_s[h])[d4] =
            ((const float4*)(w + ((size_t)(h * LLn + l)) * DDn))[d4];
    }
    __syncthreads();

    const int j  = __brev((unsigned)lane) >> 27;
    const int jb = j >> 3, jh = j & 7;

    const int bs0 = quarter * 32 + warp * 4;
    u64 acc[4][HHn];
    #pragma unroll
    for (int b = 0; b < 4; b++)
        #pragma unroll
        for (int h = 0; h < HHn; h++) acc[b][h] = 0ull;

    #pragma unroll
    for (int c = 0; c < 4; c++) {
        const int d4 = c * 32 + lane;
        u64 xp[4][2];
        #pragma unroll
        for (int b = 0; b < 4; b++) {
            double2 xv = ((const double2*)
                (x + ((size_t)((bs0 + b) * LLn + l)) * DDn))[d4];
            xp[b][0] = __double_as_longlong(xv.x);
            xp[b][1] = __double_as_longlong(xv.y);
        }
        #pragma unroll
        for (int h = 0; h < HHn; h++) {
            double2 wv = ((const double2*)w_s[h])[d4];
            u64 w0 = __double_as_longlong(wv.x);
            u64 w1v = __double_as_longlong(wv.y);
            #pragma unroll
            for (int b = 0; b < 4; b++) {
                fma2(acc[b][h], xp[b][0], w0);
                fma2(acc[b][h], xp[b][1], w1v);
            }
        }
    }
    float vals[32];
    #pragma unroll
    for (int b = 0; b < 4; b++)
        #pragma unroll
        for (int h = 0; h < HHn; h++) {
            float2 p = upk2(acc[b][h]);
            vals[b * 8 + h] = p.x + p.y;
        }
    #pragma unroll
    for (int s = 0; s < 5; s++) {
        const int n = 32 >> s;
        const int off = 1 << s;
        const bool up = (lane & off) != 0;
        #pragma unroll
        for (int i = 0; i < (n >> 1); i++) {
            float kept = up ? vals[i + (n >> 1)] : vals[i];
            float sent = up ? vals[i] : vals[i + (n >> 1)];
            float r = __shfl_xor_sync(0xffffffffu, sent, off);
            vals[i] = kept + r;
        }
    }
    logits[((size_t)(bs0 + jb) * HHn + jh) * LLn + l] = vals[0];
}

// ---------------------------------------------------------------------------
// K2: fused softmax + ax. grid (bs=128, dhalf=2), block 256. fp16 out.
// ---------------------------------------------------------------------------
__global__ __launch_bounds__(256) void ax_kernel(
    const float* __restrict__ x, const float* __restrict__ logits,
    const int* __restrict__ mask, float* __restrict__ attn_out,
    __half* __restrict__ axh)
{
    __shared__ float  a_s[HHn][LLn];
    __shared__ __align__(8) float2 ap[LLn][HHn/2];
    const int bs = blockIdx.x, dh = blockIdx.y;
    const int tid = threadIdx.x, warp = tid >> 5, lane = tid & 31;

    {
        const int h = warp;
        const int row = bs * HHn + h;
        const float invT = 0.0441941738241592f;
        float v[4], mx = -3.4e38f;
        #pragma unroll
        for (int i = 0; i < 4; i++) {
            int l = lane + 32 * i;
            float lg = logits[(size_t)row * LLn + l] * invT;
            if (mask[bs * LLn + l] == 0) lg = -1e9f;
            v[i] = lg; mx = fmaxf(mx, lg);
        }
        #pragma unroll
        for (int off = 16; off; off >>= 1)
            mx = fmaxf(mx, __shfl_xor_sync(0xffffffffu, mx, off));
        float sum = 0.f;
        #pragma unroll
        for (int i = 0; i < 4; i++) { v[i] = __expf(v[i] - mx); sum += v[i]; }
        #pragma unroll
        for (int off = 16; off; off >>= 1)
            sum += __shfl_xor_sync(0xffffffffu, sum, off);
        float inv = 1.f / sum;
        #pragma unroll
        for (int i = 0; i < 4; i++) {
            int l = lane + 32 * i;
            float a = v[i] * inv;
            a_s[h][l] = a;
            if (dh == 0 && attn_out) attn_out[(size_t)row * LLn + l] = a;
        }
    }
    __syncthreads();

    #pragma unroll
    for (int i = tid; i < LLn * 4; i += 256) {
        int l = i >> 2, p = i & 3;
        ap[l][p] = make_float2(a_s[2 * p][l], a_s[2 * p + 1][l]);
    }
    __syncthreads();

    const int d = dh * 256 + tid;
    const float* xp = x + (size_t)bs * LLn * DDn + d;

    u64 acc[4];
    #pragma unroll
    for (int p = 0; p < 4; p++) acc[p] = 0ull;

    #pragma unroll 8
    for (int l = 0; l < LLn; l++) {
        float xv = xp[(size_t)l * DDn];
        u64 xx = pk2(xv, xv);
        #pragma unroll
        for (int p = 0; p < 4; p++) {
            u64 av = __double_as_longlong(*(const double*)&ap[l][p]);
            fma2(acc[p], av, xx);
        }
    }
    #pragma unroll
    for (int p = 0; p < 4; p++) {
        float2 s = upk2(acc[p]);
        size_t o0 = ((size_t)bs * HHn + 2 * p) * DDn + d;
        size_t o1 = ((size_t)bs * HHn + 2 * p + 1) * DDn + d;
        axh[o0] = __float2half(s.x);
        axh[o1] = __float2half(s.y);
    }
}

// ---------------------------------------------------------------------------
// LayerNorm over fp16 partials. 4 warps/row, 4 elems/thread (8 loads MLP).
// grid NROW/2 (2 rows/block). Optional fp32 out + fp16 out.
// ---------------------------------------------------------------------------
template<int NPART, bool ADDBIAS, bool RES, bool SPLIT>
__global__ __launch_bounds__(256) void ln_kernel(
    const __half* __restrict__ parts, const float* __restrict__ bias,
    const float* __restrict__ res,
    const float* __restrict__ g, const float* __restrict__ b,
    float* __restrict__ out, __half* __restrict__ oh)
{
    __shared__ float red[8][2];
    const int warp = threadIdx.x >> 5, lane = threadIdx.x & 31;
    const int wp = warp >> 2, qw = warp & 3;
    const int row = blockIdx.x * 2 + wp;
    const int off = qw * 128 + lane * 4;
    const size_t base = (size_t)row * DDn + off;

    float v[4] = { 0.f, 0.f, 0.f, 0.f };
    #pragma unroll
    for (int p = 0; p < NPART; p++) {
        uint2 u = *(const uint2*)(parts + (size_t)p * NROW * DDn + base);
        float2 f0 = __half22float2(*(__half2*)&u.x);
        float2 f1 = __half22float2(*(__half2*)&u.y);
        v[0] += f0.x; v[1] += f0.y; v[2] += f1.x; v[3] += f1.y;
    }
    if (ADDBIAS) {
        float4 a = *(const float4*)(bias + off);
        v[0] += a.x; v[1] += a.y; v[2] += a.z; v[3] += a.w;
    }
    if (RES) {
        float4 a = *(const float4*)(res + base);
        v[0] += a.x; v[1] += a.y; v[2] += a.z; v[3] += a.w;
    }

    float s = v[0] + v[1] + v[2] + v[3];
    float sq = v[0]*v[0] + v[1]*v[1] + v[2]*v[2] + v[3]*v[3];
    #pragma unroll
    for (int o2 = 16; o2; o2 >>= 1) {
        s  += __shfl_xor_sync(0xffffffffu, s,  o2);
        sq += __shfl_xor_sync(0xffffffffu, sq, o2);
    }
    if (lane == 0) { red[warp][0] = s; red[warp][1] = sq; }
    __syncthreads();
    float ts = red[wp*4+0][0] + red[wp*4+1][0] + red[wp*4+2][0] + red[wp*4+3][0];
    float tq = red[wp*4+0][1] + red[wp*4+1][1] + red[wp*4+2][1] + red[wp*4+3][1];
    float mu  = ts * (1.f / DDn);
    float var = tq * (1.f / DDn) - mu * mu;
    float inv = rsqrtf(var + 1e-6f);

    float4 gv = *(const float4*)(g + off);
    float4 bv = *(const float4*)(b + off);
    float y0 = (v[0] - mu) * inv * gv.x + bv.x;
    float y1 = (v[1] - mu) * inv * gv.y + bv.y;
    float y2 = (v[2] - mu) * inv * gv.z + bv.z;
    float y3 = (v[3] - mu) * inv * gv.w + bv.w;
    if (out)
        *(float4*)(out + base) = make_float4(y0, y1, y2, y3);
    if (SPLIT) {
        __half2 h0 = __floats2half2_rn(y0, y1);
        __half2 h1 = __floats2half2_rn(y2, y3);
        uint2 hu;
        hu.x = *(uint32_t*)&h0; hu.y = *(uint32_t*)&h1;
        *(uint2*)(oh + base) = hu;
    }
}

// ---------------------------------------------------------------------------
extern "C" void kernel_launch(void* const* d_in, const int* in_sizes, int n_in,
                              void* d_out, int out_size)
{
    const float* x    = (const float*)d_in[0];
    const int*   mask = (const int*)  d_in[1];
    const float* w    = (const float*)d_in[2];
    const float* v_w  = (const float*)d_in[3];
    const float* ln_g = (const float*)d_in[4];
    const float* ln_b = (const float*)d_in[5];
    const float* w1   = (const float*)d_in[6];
    const float* b1   = (const float*)d_in[7];
    const float* w2   = (const float*)d_in[8];
    const float* b2   = (const float*)d_in[9];
    const float* fg   = (const float*)d_in[10];
    const float* fb   = (const float*)d_in[11];

    float *o, *lg;
    __half *pp, *axh, *oh, *hh, *vwf, *w1f, *w2f;
    cudaGetSymbolAddress((void**)&o,   g_o);
    cudaGetSymbolAddress((void**)&lg,  g_logits);
    cudaGetSymbolAddress((void**)&pp,  g_p);
    cudaGetSymbolAddress((void**)&axh, g_axh);
    cudaGetSymbolAddress((void**)&oh,  g_oh);
    cudaGetSymbolAddress((void**)&hh,  g_hh);
    cudaGetSymbolAddress((void**)&vwf, g_vwf);
    cudaGetSymbolAddress((void**)&w1f, g_w1f);
    cudaGetSymbolAddress((void**)&w2f, g_w2f);

    float* y_out = (float*)d_out;
    float* attn_out = (out_size >= NROW * DDn + NROW * LLn)
                        ? (y_out + NROW * DDn) : nullptr;

    constexpr int SMG = 4 * (128 * 64 + 128 * 64);   // 65536
    cudaFuncSetAttribute(gemm_mma<0>,
                         cudaFuncAttributeMaxDynamicSharedMemorySize, SMG);
    cudaFuncSetAttribute(gemm_mma<1>,
                         cudaFuncAttributeMaxDynamicSharedMemorySize, SMG);

    // K1 union: logits (512 blocks) + weight conversion (576 blocks, MLP 4)
    logits_conv_kernel<<<512 + 576, 256>>>(
        x, w, lg, (const float4*)v_w, (const float4*)w1, (const float4*)w2,
        vwf, w1f, w2f);

    // K2: fused softmax + attn@x (fp16 out)
    ax_kernel<<<dim3(NBS, 2), 256>>>(x, lg, mask, attn_out, axh);

    // G0: axh @ vwf^T, split-K4 -> fp16 p0..p3  (1024 x 512 x 512)
    gemm_mma<0><<<dim3(DDn/128, NROW/128, 4), 256, SMG>>>(
        axh, vwf, nullptr, pp, NROW, DDn, DDn);

    // o = LN(p0..p3) (+ fp16 out)
    ln_kernel<4, false, false, true><<<NROW/2, 256>>>(
        pp, nullptr, nullptr, ln_g, ln_b, o, oh);

    // G1: hh = fp16(relu(oh @ w1f^T + b1))  (1024 x 2048 x 512)
    gemm_mma<1><<<dim3(DIn/128, NROW/128, 1), 256, SMG>>>(
        oh, w1f, b1, hh, NROW, DIn, DDn);

    // G2: hh @ w2f^T, split-K4 -> fp16 p0..p3  (1024 x 512 x 2048)
    gemm_mma<0><<<dim3(DDn/128, NROW/128, 4), 256, SMG>>>(
        hh, w2f, nullptr, pp, NROW, DDn, DIn);

    // y = LN(sum p + b2 + o)
    ln_kernel<4, true, true, false><<<NROW/2, 256>>>(
        pp, b2, o, fg, fb, y_out, nullptr);
}